// round 8
// baseline (speedup 1.0000x reference)
#include <cuda_runtime.h>
#include <math.h>
#include <stdint.h>

#define Nn 100000
#define Ee 800000
#define FIN 128
#define H1  256
#define OUTD 128

// ---------------- scratch (static device globals) ----------------
__device__ float g_G[(size_t)Nn * H1];     // fused GEMM output: gates pre-aggregation [N,256]
__device__ float g_deg[Nn];
__device__ float g_dinv[Nn];
__device__ int   g_count[Nn];
__device__ int   g_rowptr[Nn];
__device__ int   g_cursor[Nn];
__device__ int2  g_csr[Ee];                // {src, __float_as_int(dinv[src]*w)}
__device__ float g_Wc[H1 * 256];           // folded weights (tf32), cols interleaved (z,h)
__device__ float g_bc[256];                // folded bias, interleaved
__device__ float g_Wb0[FIN * H1];          // tf32-rounded fc0_w
__device__ int   g_bsums[128];

// ---------------- helpers ----------------
__device__ __forceinline__ float to_tf32(float x) {
    float r;
    asm("cvt.rna.tf32.f32 %0, %1;" : "=f"(r) : "f"(x));
    return r;
}

__device__ __forceinline__ void mma_tf32(float* c, const uint32_t* a, const uint32_t* b) {
    asm volatile(
        "mma.sync.aligned.m16n8k8.row.col.f32.tf32.tf32.f32 "
        "{%0,%1,%2,%3},{%4,%5,%6,%7},{%8,%9},{%0,%1,%2,%3};\n"
        : "+f"(c[0]), "+f"(c[1]), "+f"(c[2]), "+f"(c[3])
        : "r"(a[0]), "r"(a[1]), "r"(a[2]), "r"(a[3]), "r"(b[0]), "r"(b[1]));
}

__device__ __forceinline__ uint32_t smem_u32(const void* p) {
    uint32_t a;
    asm("{ .reg .u64 t; cvta.to.shared.u64 t, %1; cvt.u32.u64 %0, t; }" : "=r"(a) : "l"(p));
    return a;
}

__device__ __forceinline__ void cp_async16(uint32_t dst, const void* src, int szbytes) {
    asm volatile("cp.async.cg.shared.global [%0], [%1], 16, %2;\n"
                 :: "r"(dst), "l"(src), "r"(szbytes));
}
#define CP_COMMIT() asm volatile("cp.async.commit_group;\n" ::: "memory")
#define CP_WAIT1()  asm volatile("cp.async.wait_group 1;\n" ::: "memory")

// ---------------- graph prep ----------------
__global__ void k_init() {
    int i = blockIdx.x * blockDim.x + threadIdx.x;
    if (i < Nn) { g_deg[i] = 1.0f; g_count[i] = 0; g_cursor[i] = 0; }
}

__global__ void k_edge_accum(const int* __restrict__ dst, const float* __restrict__ ew) {
    int e = blockIdx.x * blockDim.x + threadIdx.x;
    if (e < Ee) {
        int d = dst[e];
        atomicAdd(&g_deg[d], ew[e]);
        atomicAdd(&g_count[d], 1);
    }
}

__global__ void k_dinv() {
    int i = blockIdx.x * blockDim.x + threadIdx.x;
    if (i < Nn) g_dinv[i] = rsqrtf(g_deg[i]);
}

__global__ void k_scan_block() {
    __shared__ int s[1024];
    int i = blockIdx.x * 1024 + threadIdx.x;
    int v = (i < Nn) ? g_count[i] : 0;
    s[threadIdx.x] = v;
    __syncthreads();
    #pragma unroll
    for (int off = 1; off < 1024; off <<= 1) {
        int t = (threadIdx.x >= off) ? s[threadIdx.x - off] : 0;
        __syncthreads();
        s[threadIdx.x] += t;
        __syncthreads();
    }
    if (i < Nn) g_rowptr[i] = s[threadIdx.x] - v;
    if (threadIdx.x == 1023) g_bsums[blockIdx.x] = s[1023];
}

__global__ void k_scan_sums(int nb) {
    if (threadIdx.x == 0 && blockIdx.x == 0) {
        int acc = 0;
        for (int b = 0; b < nb; b++) { int t = g_bsums[b]; g_bsums[b] = acc; acc += t; }
    }
}

__global__ void k_scan_add() {
    int i = blockIdx.x * 1024 + threadIdx.x;
    if (i < Nn) g_rowptr[i] += g_bsums[blockIdx.x];
}

__global__ void k_fill(const int* __restrict__ src, const int* __restrict__ dst,
                       const float* __restrict__ ew) {
    int e = blockIdx.x * blockDim.x + threadIdx.x;
    if (e < Ee) {
        int d = dst[e], s = src[e];
        int pos = g_rowptr[d] + atomicAdd(&g_cursor[d], 1);
        g_csr[pos] = make_int2(s, __float_as_int(g_dinv[s] * ew[e]));
    }
}

// ---------------- weight prep ----------------
__global__ void k_round_b0(const float* __restrict__ w) {
    int i = blockIdx.x * blockDim.x + threadIdx.x;
    if (i < FIN * H1) g_Wb0[i] = to_tf32(w[i]);
}

__global__ void k_build_wc(const float* __restrict__ czw, const float* __restrict__ chw,
                           const float* __restrict__ lzw, const float* __restrict__ lhw) {
    __shared__ float rz[128], rh[128];
    int k = blockIdx.x;
    int j = threadIdx.x;
    rz[j] = czw[k * 128 + j];
    rh[j] = chw[k * 128 + j];
    __syncthreads();
    float az = 0.f, ah = 0.f;
    #pragma unroll 4
    for (int t = 0; t < 128; t++) {
        az += rz[t] * lzw[t * 128 + j];
        ah += rh[t] * lhw[t * 128 + j];
    }
    g_Wc[k * 256 + 2 * j]     = to_tf32(az);
    g_Wc[k * 256 + 2 * j + 1] = to_tf32(ah);
}

__global__ void k_build_bc(const float* __restrict__ czb, const float* __restrict__ chb,
                           const float* __restrict__ lzw, const float* __restrict__ lhw,
                           const float* __restrict__ lzb, const float* __restrict__ lhb) {
    int j = threadIdx.x;
    float az = lzb[j], ah = lhb[j];
    #pragma unroll 4
    for (int t = 0; t < 128; t++) {
        az += czb[t] * lzw[t * 128 + j];
        ah += chb[t] * lhw[t * 128 + j];
    }
    g_bc[2 * j]     = az;
    g_bc[2 * j + 1] = ah;
}

// ---------------- fused double-GEMM: G = rna(relu(x@W0+b)) @ Wc ----------------
// (round-6 proven kernel, unchanged)
#define ASA_OFF 0
#define ASA_SZ  (64 * 36)
#define BSA_OFF 4608
#define BSA_SZ  (32 * 264)
#define AS2_OFF 0
#define AS2_LD  260
#define BSB_OFF 16640
#define BSB_SZ  (16 * 264)
#define SMEM_FLOATS 25088

__global__ __launch_bounds__(256, 2) void k_gemm_fused(const float* __restrict__ x,
                                                       const float* __restrict__ bias0,
                                                       int M) {
    extern __shared__ float sm[];

    const int tid  = threadIdx.x;
    const int lane = tid & 31;
    const int w    = tid >> 5;
    const int wy   = w & 1;
    const int wx   = w >> 1;
    const int g    = lane >> 2;
    const int cq   = lane & 3;

    const int row0  = blockIdx.x * 64;
    const int woffm = wy * 32;
    const int woffn = wx * 64;

    const uint32_t smb = smem_u32(sm);

    float acc[2][8][4];
    #pragma unroll
    for (int mt = 0; mt < 2; mt++)
        #pragma unroll
        for (int nt = 0; nt < 8; nt++)
            #pragma unroll
            for (int i = 0; i < 4; i++) acc[mt][nt][i] = 0.f;

    // ---- stage A: Xt_tile = relu(x[row0:row0+64, :] @ W0 + b), K=128 ----
    auto load_a = [&](int st, int kb) {
        #pragma unroll
        for (int l = 0; l < 2; l++) {
            int idx = tid + l * 256;
            int r  = idx >> 3;
            int kc = (idx & 7) << 2;
            int gr = row0 + r;
            int ok = (gr < M);
            const float* gp = x + (size_t)(ok ? gr : (M - 1)) * FIN + kb + kc;
            cp_async16(smb + (uint32_t)(ASA_OFF + st * ASA_SZ + r * 36 + kc) * 4u, gp, ok ? 16 : 0);
        }
        #pragma unroll
        for (int l = 0; l < 8; l++) {
            int idx = tid + l * 256;
            int k  = idx >> 6;
            int nc = (idx & 63) << 2;
            cp_async16(smb + (uint32_t)(BSA_OFF + st * BSA_SZ + k * 264 + nc) * 4u,
                       g_Wb0 + (size_t)(kb + k) * 256 + nc, 16);
        }
    };

    load_a(0, 0);
    CP_COMMIT();

    for (int kbi = 0; kbi < 4; kbi++) {
        if (kbi + 1 < 4) load_a((kbi + 1) & 1, (kbi + 1) * 32);
        CP_COMMIT();
        CP_WAIT1();
        __syncthreads();
        const float* as = sm + ASA_OFF + (kbi & 1) * ASA_SZ;
        const float* bs = sm + BSA_OFF + (kbi & 1) * BSA_SZ;

        #pragma unroll
        for (int kk = 0; kk < 32; kk += 8) {
            uint32_t af[2][4], bf[8][2];
            #pragma unroll
            for (int mt = 0; mt < 2; mt++) {
                int mb = woffm + mt * 16;
                af[mt][0] = __float_as_uint(to_tf32(as[(mb + g)     * 36 + kk + cq]));
                af[mt][1] = __float_as_uint(to_tf32(as[(mb + g + 8) * 36 + kk + cq]));
                af[mt][2] = __float_as_uint(to_tf32(as[(mb + g)     * 36 + kk + cq + 4]));
                af[mt][3] = __float_as_uint(to_tf32(as[(mb + g + 8) * 36 + kk + cq + 4]));
            }
            #pragma unroll
            for (int nt = 0; nt < 8; nt++) {
                int n = woffn + nt * 8 + g;
                bf[nt][0] = __float_as_uint(bs[(kk + cq)     * 264 + n]);
                bf[nt][1] = __float_as_uint(bs[(kk + cq + 4) * 264 + n]);
            }
            #pragma unroll
            for (int mt = 0; mt < 2; mt++)
                #pragma unroll
                for (int nt = 0; nt < 8; nt++)
                    mma_tf32(acc[mt][nt], af[mt], bf[nt]);
        }
        __syncthreads();
    }

    // stage-A epilogue: relu + bias + tf32-round, into As2 (local rows 0..63)
    #pragma unroll
    for (int mt = 0; mt < 2; mt++) {
        int r0 = woffm + mt * 16 + g;
        int r1 = r0 + 8;
        #pragma unroll
        for (int nt = 0; nt < 8; nt++) {
            int col = woffn + nt * 8 + 2 * cq;
            float b0 = bias0[col], b1 = bias0[col + 1];
            sm[AS2_OFF + r0 * AS2_LD + col]     = to_tf32(fmaxf(acc[mt][nt][0] + b0, 0.f));
            sm[AS2_OFF + r0 * AS2_LD + col + 1] = to_tf32(fmaxf(acc[mt][nt][1] + b1, 0.f));
            sm[AS2_OFF + r1 * AS2_LD + col]     = to_tf32(fmaxf(acc[mt][nt][2] + b0, 0.f));
            sm[AS2_OFF + r1 * AS2_LD + col + 1] = to_tf32(fmaxf(acc[mt][nt][3] + b1, 0.f));
        }
    }
    __syncthreads();

    // ---- stage B: G_tile = Xt_tile @ Wc, K=256, A from smem ----
    #pragma unroll
    for (int mt = 0; mt < 2; mt++)
        #pragma unroll
        for (int nt = 0; nt < 8; nt++)
            #pragma unroll
            for (int i = 0; i < 4; i++) acc[mt][nt][i] = 0.f;

    auto load_b = [&](int st, int kc) {
        #pragma unroll
        for (int l = 0; l < 4; l++) {
            int idx = tid + l * 256;
            int k  = idx >> 6;
            int nc = (idx & 63) << 2;
            cp_async16(smb + (uint32_t)(BSB_OFF + st * BSB_SZ + k * 264 + nc) * 4u,
                       g_Wc + (size_t)(kc + k) * 256 + nc, 16);
        }
    };

    load_b(0, 0);
    CP_COMMIT();

    for (int it = 0; it < 16; it++) {
        if (it + 1 < 16) load_b((it + 1) & 1, (it + 1) * 16);
        CP_COMMIT();
        CP_WAIT1();
        __syncthreads();
        const float* bs = sm + BSB_OFF + (it & 1) * BSB_SZ;
        const float* a2 = sm + AS2_OFF;
        const int kg = it * 16;

        #pragma unroll
        for (int kk = 0; kk < 16; kk += 8) {
            uint32_t af[2][4], bf[8][2];
            #pragma unroll
            for (int mt = 0; mt < 2; mt++) {
                int mb = woffm + mt * 16;
                af[mt][0] = __float_as_uint(a2[(mb + g)     * AS2_LD + kg + kk + cq]);
                af[mt][1] = __float_as_uint(a2[(mb + g + 8) * AS2_LD + kg + kk + cq]);
                af[mt][2] = __float_as_uint(a2[(mb + g)     * AS2_LD + kg + kk + cq + 4]);
                af[mt][3] = __float_as_uint(a2[(mb + g + 8) * AS2_LD + kg + kk + cq + 4]);
            }
            #pragma unroll
            for (int nt = 0; nt < 8; nt++) {
                int n = woffn + nt * 8 + g;
                bf[nt][0] = __float_as_uint(bs[(kk + cq)     * 264 + n]);
                bf[nt][1] = __float_as_uint(bs[(kk + cq + 4) * 264 + n]);
            }
            #pragma unroll
            for (int mt = 0; mt < 2; mt++)
                #pragma unroll
                for (int nt = 0; nt < 8; nt++)
                    mma_tf32(acc[mt][nt], af[mt], bf[nt]);
        }
        __syncthreads();
    }

    // stage-B epilogue: raw gates to g_G (guarded)
    #pragma unroll
    for (int mt = 0; mt < 2; mt++) {
        int r0 = row0 + woffm + mt * 16 + g;
        int r1 = r0 + 8;
        #pragma unroll
        for (int nt = 0; nt < 8; nt++) {
            int col = woffn + nt * 8 + 2 * cq;
            if (r0 < M)
                *(float2*)(g_G + (size_t)r0 * 256 + col) = make_float2(acc[mt][nt][0], acc[mt][nt][1]);
            if (r1 < M)
                *(float2*)(g_G + (size_t)r1 * 256 + col) = make_float2(acc[mt][nt][2], acc[mt][nt][3]);
        }
    }
}

// ---------------- fused aggregate + bias + GRU + output head ----------------
// Warp-per-node, FEATURE-SPLIT into 2 passes of 128 gate features (512 B/row).
// Per-pass touched G region = 51 MB < L2 -> gathers become L2 hits after first touch.
// PASS p: gate features [128p, 128p+128) = h columns [64p, 64p+64).
template<int PASS>
__global__ __launch_bounds__(256) void k_agg_gru(const float* __restrict__ fcw,
                                                 const float* __restrict__ fcb,
                                                 float* __restrict__ hout,
                                                 float* __restrict__ out) {
    const int wid  = threadIdx.x >> 5;
    const int lane = threadIdx.x & 31;
    const int n    = blockIdx.x * 8 + wid;
    if (n >= Nn) return;

    const float4* G4 = (const float4*)g_G;        // row stride 64 float4
    const int co = PASS * 32 + lane;              // float4 column within row

    float4 a = make_float4(0.f, 0.f, 0.f, 0.f);

    const int beg = g_rowptr[n];
    const int count = g_count[n];
    const int nf = count < 32 ? count : 32;

    int2 my = make_int2(0, 0);
    if (lane < nf) my = g_csr[beg + lane];

    int e = 0;
    for (; e + 4 <= nf; e += 4) {
        int s0 = __shfl_sync(0xffffffffu, my.x, e);
        int s1 = __shfl_sync(0xffffffffu, my.x, e + 1);
        int s2 = __shfl_sync(0xffffffffu, my.x, e + 2);
        int s3 = __shfl_sync(0xffffffffu, my.x, e + 3);
        float c0 = __int_as_float(__shfl_sync(0xffffffffu, my.y, e));
        float c1 = __int_as_float(__shfl_sync(0xffffffffu, my.y, e + 1));
        float c2 = __int_as_float(__shfl_sync(0xffffffffu, my.y, e + 2));
        float c3 = __int_as_float(__shfl_sync(0xffffffffu, my.y, e + 3));
        float4 u0 = G4[(size_t)s0 * 64 + co];
        float4 u1 = G4[(size_t)s1 * 64 + co];
        float4 u2 = G4[(size_t)s2 * 64 + co];
        float4 u3 = G4[(size_t)s3 * 64 + co];
        a.x += c0*u0.x + c1*u1.x + c2*u2.x + c3*u3.x;
        a.y += c0*u0.y + c1*u1.y + c2*u2.y + c3*u3.y;
        a.z += c0*u0.z + c1*u1.z + c2*u2.z + c3*u3.z;
        a.w += c0*u0.w + c1*u1.w + c2*u2.w + c3*u3.w;
    }
    for (; e < nf; e++) {
        int   s = __shfl_sync(0xffffffffu, my.x, e);
        float c = __int_as_float(__shfl_sync(0xffffffffu, my.y, e));
        float4 u = G4[(size_t)s * 64 + co];
        a.x += c*u.x; a.y += c*u.y; a.z += c*u.z; a.w += c*u.w;
    }
    for (int ee = 32; ee < count; ee++) {         // ~never taken (Poisson(8))
        int2 p = g_csr[beg + ee];
        float c = __int_as_float(p.y);
        float4 u = G4[(size_t)p.x * 64 + co];
        a.x += c*u.x; a.y += c*u.y; a.z += c*u.z; a.w += c*u.w;
    }

    const float di  = g_dinv[n];
    const float di2 = di * di;
    float4 self = G4[(size_t)n * 64 + co];
    float4 bc   = ((const float4*)g_bc)[co];

    float gz0 = a.x * di + di2 * self.x + bc.x;
    float gh0 = a.y * di + di2 * self.y + bc.y;
    float gz1 = a.z * di + di2 * self.z + bc.z;
    float gh1 = a.w * di + di2 * self.w + bc.w;

    float h0 = (1.f - 1.f / (1.f + expf(-gz0))) * tanhf(gh0);
    float h1 = (1.f - 1.f / (1.f + expf(-gz1))) * tanhf(gh1);

    *(float2*)(hout + (size_t)n * 128 + PASS * 64 + 2 * lane) = make_float2(h0, h1);

    float2 wv = ((const float2*)fcw)[PASS * 32 + lane];
    float prod = fmaxf(h0, 0.f) * wv.x + fmaxf(h1, 0.f) * wv.y;
    #pragma unroll
    for (int o = 16; o; o >>= 1) prod += __shfl_xor_sync(0xffffffffu, prod, o);
    if (lane == 0) {
        if (PASS == 0) out[n] = prod + fcb[0];
        else           out[n] += prod;
    }
}

// ---------------- launch ----------------
extern "C" void kernel_launch(void* const* d_in, const int* in_sizes, int n_in,
                              void* d_out, int out_size) {
    const float* x     = (const float*)d_in[0];
    const int*   ei    = (const int*)d_in[1];
    const float* ew    = (const float*)d_in[2];
    const float* fc0_w = (const float*)d_in[3];
    const float* fc0_b = (const float*)d_in[4];
    // d_in[5] = att: softmax over one element == 1.0
    const float* czw   = (const float*)d_in[6];
    const float* czb   = (const float*)d_in[7];
    const float* lzw   = (const float*)d_in[8];
    const float* lzb   = (const float*)d_in[9];
    // d_in[10..13] dead (H0 == 0 kills the R branch)
    const float* chw   = (const float*)d_in[14];
    const float* chb   = (const float*)d_in[15];
    const float* lhw   = (const float*)d_in[16];
    const float* lhb   = (const float*)d_in[17];
    const float* fcw   = (const float*)d_in[18];
    const float* fcb   = (const float*)d_in[19];

    const int* src = ei;
    const int* dst = ei + Ee;

    float* out  = (float*)d_out;
    float* hout = out + Nn;

    const int nb = (Nn + 1023) / 1024;
    const int gM = (Nn + 63) / 64;
    const int smem_bytes = SMEM_FLOATS * 4;

    static bool attr_done = false;
    if (!attr_done) {
        cudaFuncSetAttribute(k_gemm_fused, cudaFuncAttributeMaxDynamicSharedMemorySize, smem_bytes);
        attr_done = true;
    }

    // launch index 3 = fused GEMM (ncu capture slot, control)
    k_round_b0<<<(FIN * H1 + 255) / 256, 256>>>(fc0_w);
    k_build_wc<<<256, 128>>>(czw, chw, lzw, lhw);
    k_build_bc<<<1, 128>>>(czb, chb, lzw, lhw, lzb, lhb);

    k_gemm_fused<<<gM, 256, smem_bytes>>>(x, fc0_b, Nn);    // index 3

    k_init<<<(Nn + 255) / 256, 256>>>();
    k_edge_accum<<<(Ee + 255) / 256, 256>>>(dst, ew);
    k_dinv<<<(Nn + 255) / 256, 256>>>();
    k_scan_block<<<nb, 1024>>>();
    k_scan_sums<<<1, 32>>>(nb);
    k_scan_add<<<nb, 1024>>>();
    k_fill<<<(Ee + 255) / 256, 256>>>(src, dst, ew);

    k_agg_gru<0><<<(Nn + 7) / 8, 256>>>(fcw, fcb, hout, out);
    k_agg_gru<1><<<(Nn + 7) / 8, 256>>>(fcw, fcb, hout, out);
}

// round 9
// speedup vs baseline: 1.0806x; 1.0806x over previous
#include <cuda_runtime.h>
#include <cuda_fp16.h>
#include <math.h>
#include <stdint.h>

#define Nn 100000
#define Ee 800000
#define FIN 128
#define H1  256
#define OUTD 128

// ---------------- scratch (static device globals) ----------------
__device__ float  g_G[(size_t)Nn * H1];    // gates pre-aggregation [N,256] fp32
__device__ __half g_Xh[(size_t)Nn * FIN];  // fp16 x
__device__ float  g_deg[Nn];
__device__ float  g_dinv[Nn];
__device__ int    g_count[Nn];
__device__ int    g_rowptr[Nn];
__device__ int    g_cursor[Nn];
__device__ int2   g_csr[Ee];               // {src, __float_as_int(dinv[src]*w)}
__device__ __half g_Wch[H1 * 256];         // folded weights [n][k] fp16, n interleaved (z,h)
__device__ float  g_bc[256];               // folded bias, interleaved
__device__ __half g_Wb0h[256 * FIN];       // fc0_w transposed [n][k] fp16
__device__ int    g_bsums[128];

// ---------------- helpers ----------------
__device__ __forceinline__ void mma_f16(float* c, const uint32_t* a, const uint32_t* b) {
    asm volatile(
        "mma.sync.aligned.m16n8k16.row.col.f32.f16.f16.f32 "
        "{%0,%1,%2,%3},{%4,%5,%6,%7},{%8,%9},{%0,%1,%2,%3};\n"
        : "+f"(c[0]), "+f"(c[1]), "+f"(c[2]), "+f"(c[3])
        : "r"(a[0]), "r"(a[1]), "r"(a[2]), "r"(a[3]), "r"(b[0]), "r"(b[1]));
}

__device__ __forceinline__ uint32_t smem_u32(const void* p) {
    uint32_t a;
    asm("{ .reg .u64 t; cvta.to.shared.u64 t, %1; cvt.u32.u64 %0, t; }" : "=r"(a) : "l"(p));
    return a;
}

__device__ __forceinline__ void cp_async16(uint32_t dst, const void* src, int szbytes) {
    asm volatile("cp.async.cg.shared.global [%0], [%1], 16, %2;\n"
                 :: "r"(dst), "l"(src), "r"(szbytes));
}
#define CP_COMMIT() asm volatile("cp.async.commit_group;\n" ::: "memory")
#define CP_WAIT1()  asm volatile("cp.async.wait_group 1;\n" ::: "memory")

// ---------------- graph prep ----------------
__global__ void k_init() {
    int i = blockIdx.x * blockDim.x + threadIdx.x;
    if (i < Nn) { g_deg[i] = 1.0f; g_count[i] = 0; g_cursor[i] = 0; }
}

__global__ void k_edge_accum(const int* __restrict__ dst, const float* __restrict__ ew) {
    int e = blockIdx.x * blockDim.x + threadIdx.x;
    if (e < Ee) {
        int d = dst[e];
        atomicAdd(&g_deg[d], ew[e]);
        atomicAdd(&g_count[d], 1);
    }
}

__global__ void k_dinv() {
    int i = blockIdx.x * blockDim.x + threadIdx.x;
    if (i < Nn) g_dinv[i] = rsqrtf(g_deg[i]);
}

__global__ void k_scan_block() {
    __shared__ int s[1024];
    int i = blockIdx.x * 1024 + threadIdx.x;
    int v = (i < Nn) ? g_count[i] : 0;
    s[threadIdx.x] = v;
    __syncthreads();
    #pragma unroll
    for (int off = 1; off < 1024; off <<= 1) {
        int t = (threadIdx.x >= off) ? s[threadIdx.x - off] : 0;
        __syncthreads();
        s[threadIdx.x] += t;
        __syncthreads();
    }
    if (i < Nn) g_rowptr[i] = s[threadIdx.x] - v;
    if (threadIdx.x == 1023) g_bsums[blockIdx.x] = s[1023];
}

__global__ void k_scan_sums(int nb) {
    if (threadIdx.x == 0 && blockIdx.x == 0) {
        int acc = 0;
        for (int b = 0; b < nb; b++) { int t = g_bsums[b]; g_bsums[b] = acc; acc += t; }
    }
}

__global__ void k_scan_add() {
    int i = blockIdx.x * 1024 + threadIdx.x;
    if (i < Nn) g_rowptr[i] += g_bsums[blockIdx.x];
}

__global__ void k_fill(const int* __restrict__ src, const int* __restrict__ dst,
                       const float* __restrict__ ew) {
    int e = blockIdx.x * blockDim.x + threadIdx.x;
    if (e < Ee) {
        int d = dst[e], s = src[e];
        int pos = g_rowptr[d] + atomicAdd(&g_cursor[d], 1);
        g_csr[pos] = make_int2(s, __float_as_int(g_dinv[s] * ew[e]));
    }
}

// ---------------- input / weight prep ----------------
__global__ void k_prep_x(const float* __restrict__ x) {
    int i = blockIdx.x * blockDim.x + threadIdx.x;
    if (i < Nn * FIN / 2) {
        float2 v = ((const float2*)x)[i];
        ((__half2*)g_Xh)[i] = __floats2half2_rn(v.x, v.y);
    }
}

// g_Wb0h[n][k] = fp16(fc0_w[k][n])   (fc0_w is [128 k][256 n] row-major)
__global__ void k_prep_b0(const float* __restrict__ w) {
    int i = blockIdx.x * blockDim.x + threadIdx.x;
    if (i < FIN * 256) {
        int n = i >> 7, k = i & 127;
        g_Wb0h[n * FIN + k] = __float2half_rn(w[k * 256 + n]);
    }
}

// g_Wch[n][k], n interleaved (2j=z, 2j+1=h)
__global__ void k_build_wc(const float* __restrict__ czw, const float* __restrict__ chw,
                           const float* __restrict__ lzw, const float* __restrict__ lhw) {
    __shared__ float rz[128], rh[128];
    int k = blockIdx.x;        // 0..255
    int j = threadIdx.x;       // 0..127
    rz[j] = czw[k * 128 + j];
    rh[j] = chw[k * 128 + j];
    __syncthreads();
    float az = 0.f, ah = 0.f;
    #pragma unroll 4
    for (int t = 0; t < 128; t++) {
        az += rz[t] * lzw[t * 128 + j];
        ah += rh[t] * lhw[t * 128 + j];
    }
    g_Wch[(2 * j)     * 256 + k] = __float2half_rn(az);
    g_Wch[(2 * j + 1) * 256 + k] = __float2half_rn(ah);
}

__global__ void k_build_bc(const float* __restrict__ czb, const float* __restrict__ chb,
                           const float* __restrict__ lzw, const float* __restrict__ lhw,
                           const float* __restrict__ lzb, const float* __restrict__ lhb) {
    int j = threadIdx.x;
    float az = lzb[j], ah = lhb[j];
    #pragma unroll 4
    for (int t = 0; t < 128; t++) {
        az += czb[t] * lzw[t * 128 + j];
        ah += chb[t] * lhw[t * 128 + j];
    }
    g_bc[2 * j]     = az;
    g_bc[2 * j + 1] = ah;
}

// ---------------- fused double-GEMM (fp16): G = relu(x@W0+b) @ Wc ----------------
// BM=64, BN=256, 8 warps (warp tile 32x64), mma.m16n8k16.f16, fp32 accum.
// B operands stored [n][k] (k-contiguous) -> "col" operand loads as aligned half2.
// smem (bytes): Asa dbl [0,10240) 64x40h; Bsa dbl [10240,51200) 256x40h;
//               As2 [0,33792) 64x264h (aliases Asa/Bsa after stage A);
//               Bsb dbl [51200,92160) 256x40h.
#define ASA_B   0
#define ASA_SZB 5120
#define BSA_B   10240
#define BSA_SZB 20480
#define AS2_B   0
#define LDA  40
#define LDB  40
#define LDA2 264
#define BSB_B   51200
#define BSB_SZB 20480
#define SMEM_BYTES 92160

__global__ __launch_bounds__(256, 2) void k_gemm_fused(const float* __restrict__ bias0,
                                                       int M) {
    extern __shared__ char sm[];
    const __half* smh = (const __half*)sm;
    const uint32_t smb = smem_u32(sm);

    const int tid  = threadIdx.x;
    const int lane = tid & 31;
    const int w    = tid >> 5;
    const int wy   = w & 1;
    const int wx   = w >> 1;
    const int g    = lane >> 2;
    const int cq   = lane & 3;

    const int row0  = blockIdx.x * 64;
    const int woffm = wy * 32;
    const int woffn = wx * 64;

    float acc[2][8][4];
    #pragma unroll
    for (int mt = 0; mt < 2; mt++)
        #pragma unroll
        for (int nt = 0; nt < 8; nt++)
            #pragma unroll
            for (int i = 0; i < 4; i++) acc[mt][nt][i] = 0.f;

    // ---- stage A loads: x tile 64x32 fp16 (1 cp16/thread) + W0t 256x32 (4/thread) ----
    auto load_a = [&](int st, int kb) {
        {
            int r = tid >> 2, q = tid & 3;
            int gr = row0 + r;
            int ok = (gr < M);
            const __half* gp = g_Xh + (size_t)(ok ? gr : (M - 1)) * FIN + kb + q * 8;
            cp_async16(smb + ASA_B + st * ASA_SZB + (uint32_t)(r * LDA + q * 8) * 2u,
                       gp, ok ? 16 : 0);
        }
        #pragma unroll
        for (int l = 0; l < 4; l++) {
            int idx = tid + l * 256;
            int n = idx >> 2, q = idx & 3;
            cp_async16(smb + BSA_B + st * BSA_SZB + (uint32_t)(n * LDB + q * 8) * 2u,
                       g_Wb0h + (size_t)n * FIN + kb + q * 8, 16);
        }
    };

    load_a(0, 0);
    CP_COMMIT();

    for (int kbi = 0; kbi < 4; kbi++) {
        if (kbi + 1 < 4) load_a((kbi + 1) & 1, (kbi + 1) * 32);
        CP_COMMIT();
        CP_WAIT1();
        __syncthreads();
        const __half* as = smh + (ASA_B + (kbi & 1) * ASA_SZB) / 2;
        const __half* bs = smh + (BSA_B + (kbi & 1) * BSA_SZB) / 2;

        #pragma unroll
        for (int kk = 0; kk < 32; kk += 16) {
            uint32_t af[2][4], bf[8][2];
            #pragma unroll
            for (int mt = 0; mt < 2; mt++) {
                int mb = woffm + mt * 16;
                af[mt][0] = *(const uint32_t*)(as + (mb + g)     * LDA + kk + 2 * cq);
                af[mt][1] = *(const uint32_t*)(as + (mb + g + 8) * LDA + kk + 2 * cq);
                af[mt][2] = *(const uint32_t*)(as + (mb + g)     * LDA + kk + 2 * cq + 8);
                af[mt][3] = *(const uint32_t*)(as + (mb + g + 8) * LDA + kk + 2 * cq + 8);
            }
            #pragma unroll
            for (int nt = 0; nt < 8; nt++) {
                int n = woffn + nt * 8 + g;
                bf[nt][0] = *(const uint32_t*)(bs + n * LDB + kk + 2 * cq);
                bf[nt][1] = *(const uint32_t*)(bs + n * LDB + kk + 2 * cq + 8);
            }
            #pragma unroll
            for (int mt = 0; mt < 2; mt++)
                #pragma unroll
                for (int nt = 0; nt < 8; nt++)
                    mma_f16(acc[mt][nt], af[mt], bf[nt]);
        }
        __syncthreads();
    }

    // start streaming Wc chunk 0 into Bsb (non-aliased) to overlap with epilogue
    {
        #pragma unroll
        for (int l = 0; l < 4; l++) {
            int idx = tid + l * 256;
            int n = idx >> 2, q = idx & 3;
            cp_async16(smb + BSB_B + (uint32_t)(n * LDB + q * 8) * 2u,
                       g_Wch + (size_t)n * 256 + q * 8, 16);
        }
        CP_COMMIT();
    }

    // stage-A epilogue: relu + bias -> fp16 -> As2 [64][264]
    #pragma unroll
    for (int mt = 0; mt < 2; mt++) {
        int r0 = woffm + mt * 16 + g;
        int r1 = r0 + 8;
        #pragma unroll
        for (int nt = 0; nt < 8; nt++) {
            int col = woffn + nt * 8 + 2 * cq;
            float b0 = bias0[col], b1 = bias0[col + 1];
            __half2 v0 = __floats2half2_rn(fmaxf(acc[mt][nt][0] + b0, 0.f),
                                           fmaxf(acc[mt][nt][1] + b1, 0.f));
            __half2 v1 = __floats2half2_rn(fmaxf(acc[mt][nt][2] + b0, 0.f),
                                           fmaxf(acc[mt][nt][3] + b1, 0.f));
            *(__half2*)(sm + AS2_B + (r0 * LDA2 + col) * 2) = v0;
            *(__half2*)(sm + AS2_B + (r1 * LDA2 + col) * 2) = v1;
        }
    }
    __syncthreads();

    // ---- stage B: G = As2 @ Wct, K=256, 8 chunks of 32 ----
    #pragma unroll
    for (int mt = 0; mt < 2; mt++)
        #pragma unroll
        for (int nt = 0; nt < 8; nt++)
            #pragma unroll
            for (int i = 0; i < 4; i++) acc[mt][nt][i] = 0.f;

    auto load_b = [&](int st, int kc) {
        #pragma unroll
        for (int l = 0; l < 4; l++) {
            int idx = tid + l * 256;
            int n = idx >> 2, q = idx & 3;
            cp_async16(smb + BSB_B + st * BSB_SZB + (uint32_t)(n * LDB + q * 8) * 2u,
                       g_Wch + (size_t)n * 256 + kc + q * 8, 16);
        }
    };

    const __half* a2 = smh + AS2_B / 2;
    for (int it = 0; it < 8; it++) {
        if (it + 1 < 8) load_b((it + 1) & 1, (it + 1) * 32);
        CP_COMMIT();
        CP_WAIT1();
        __syncthreads();
        const __half* bs = smh + (BSB_B + (it & 1) * BSB_SZB) / 2;
        const int kg = it * 32;

        #pragma unroll
        for (int kk = 0; kk < 32; kk += 16) {
            uint32_t af[2][4], bf[8][2];
            #pragma unroll
            for (int mt = 0; mt < 2; mt++) {
                int mb = woffm + mt * 16;
                af[mt][0] = *(const uint32_t*)(a2 + (mb + g)     * LDA2 + kg + kk + 2 * cq);
                af[mt][1] = *(const uint32_t*)(a2 + (mb + g + 8) * LDA2 + kg + kk + 2 * cq);
                af[mt][2] = *(const uint32_t*)(a2 + (mb + g)     * LDA2 + kg + kk + 2 * cq + 8);
                af[mt][3] = *(const uint32_t*)(a2 + (mb + g + 8) * LDA2 + kg + kk + 2 * cq + 8);
            }
            #pragma unroll
            for (int nt = 0; nt < 8; nt++) {
                int n = woffn + nt * 8 + g;
                bf[nt][0] = *(const uint32_t*)(bs + n * LDB + kk + 2 * cq);
                bf[nt][1] = *(const uint32_t*)(bs + n * LDB + kk + 2 * cq + 8);
            }
            #pragma unroll
            for (int mt = 0; mt < 2; mt++)
                #pragma unroll
                for (int nt = 0; nt < 8; nt++)
                    mma_f16(acc[mt][nt], af[mt], bf[nt]);
        }
        __syncthreads();
    }

    // stage-B epilogue: raw fp32 gates to g_G (guarded)
    #pragma unroll
    for (int mt = 0; mt < 2; mt++) {
        int r0 = row0 + woffm + mt * 16 + g;
        int r1 = r0 + 8;
        #pragma unroll
        for (int nt = 0; nt < 8; nt++) {
            int col = woffn + nt * 8 + 2 * cq;
            if (r0 < M)
                *(float2*)(g_G + (size_t)r0 * 256 + col) = make_float2(acc[mt][nt][0], acc[mt][nt][1]);
            if (r1 < M)
                *(float2*)(g_G + (size_t)r1 * 256 + col) = make_float2(acc[mt][nt][2], acc[mt][nt][3]);
        }
    }
}

// ---------------- fused aggregate + bias + GRU + output head (warp-per-node) ----------------
// (round-6 proven kernel, single pass)
__global__ __launch_bounds__(256) void k_agg_gru(const float* __restrict__ fcw,
                                                 const float* __restrict__ fcb,
                                                 float* __restrict__ hout,
                                                 float* __restrict__ out) {
    const int wid  = threadIdx.x >> 5;
    const int lane = threadIdx.x & 31;
    const int n    = blockIdx.x * 8 + wid;
    if (n >= Nn) return;

    const float4* G4 = (const float4*)g_G;
    const size_t rb = (size_t)n * 64;

    float4 a0 = make_float4(0.f, 0.f, 0.f, 0.f);
    float4 a1 = make_float4(0.f, 0.f, 0.f, 0.f);

    const int beg = g_rowptr[n];
    const int count = g_count[n];
    const int nf = count < 32 ? count : 32;

    int2 my = make_int2(0, 0);
    if (lane < nf) my = g_csr[beg + lane];

    int e = 0;
    for (; e + 4 <= nf; e += 4) {
        int s0 = __shfl_sync(0xffffffffu, my.x, e);
        int s1 = __shfl_sync(0xffffffffu, my.x, e + 1);
        int s2 = __shfl_sync(0xffffffffu, my.x, e + 2);
        int s3 = __shfl_sync(0xffffffffu, my.x, e + 3);
        float c0 = __int_as_float(__shfl_sync(0xffffffffu, my.y, e));
        float c1 = __int_as_float(__shfl_sync(0xffffffffu, my.y, e + 1));
        float c2 = __int_as_float(__shfl_sync(0xffffffffu, my.y, e + 2));
        float c3 = __int_as_float(__shfl_sync(0xffffffffu, my.y, e + 3));
        float4 u0 = G4[(size_t)s0 * 64 + lane], v0 = G4[(size_t)s0 * 64 + 32 + lane];
        float4 u1 = G4[(size_t)s1 * 64 + lane], v1 = G4[(size_t)s1 * 64 + 32 + lane];
        float4 u2 = G4[(size_t)s2 * 64 + lane], v2 = G4[(size_t)s2 * 64 + 32 + lane];
        float4 u3 = G4[(size_t)s3 * 64 + lane], v3 = G4[(size_t)s3 * 64 + 32 + lane];
        a0.x += c0*u0.x + c1*u1.x + c2*u2.x + c3*u3.x;
        a0.y += c0*u0.y + c1*u1.y + c2*u2.y + c3*u3.y;
        a0.z += c0*u0.z + c1*u1.z + c2*u2.z + c3*u3.z;
        a0.w += c0*u0.w + c1*u1.w + c2*u2.w + c3*u3.w;
        a1.x += c0*v0.x + c1*v1.x + c2*v2.x + c3*v3.x;
        a1.y += c0*v0.y + c1*v1.y + c2*v2.y + c3*v3.y;
        a1.z += c0*v0.z + c1*v1.z + c2*v2.z + c3*v3.z;
        a1.w += c0*v0.w + c1*v1.w + c2*v2.w + c3*v3.w;
    }
    for (; e < nf; e++) {
        int   s = __shfl_sync(0xffffffffu, my.x, e);
        float c = __int_as_float(__shfl_sync(0xffffffffu, my.y, e));
        float4 u = G4[(size_t)s * 64 + lane], v = G4[(size_t)s * 64 + 32 + lane];
        a0.x += c*u.x; a0.y += c*u.y; a0.z += c*u.z; a0.w += c*u.w;
        a1.x += c*v.x; a1.y += c*v.y; a1.z += c*v.z; a1.w += c*v.w;
    }
    for (int ee = 32; ee < count; ee++) {
        int2 p = g_csr[beg + ee];
        float c = __int_as_float(p.y);
        float4 u = G4[(size_t)p.x * 64 + lane], v = G4[(size_t)p.x * 64 + 32 + lane];
        a0.x += c*u.x; a0.y += c*u.y; a0.z += c*u.z; a0.w += c*u.w;
        a1.x += c*v.x; a1.y += c*v.y; a1.z += c*v.z; a1.w += c*v.w;
    }

    const float di  = g_dinv[n];
    const float di2 = di * di;
    float4 self0 = G4[rb + lane], self1 = G4[rb + 32 + lane];
    float4 bc0 = ((const float4*)g_bc)[lane];
    float4 bc1 = ((const float4*)g_bc)[32 + lane];

    float gz0 = a0.x * di + di2 * self0.x + bc0.x;
    float gh0 = a0.y * di + di2 * self0.y + bc0.y;
    float gz1 = a0.z * di + di2 * self0.z + bc0.z;
    float gh1 = a0.w * di + di2 * self0.w + bc0.w;
    float gz2 = a1.x * di + di2 * self1.x + bc1.x;
    float gh2 = a1.y * di + di2 * self1.y + bc1.y;
    float gz3 = a1.z * di + di2 * self1.z + bc1.z;
    float gh3 = a1.w * di + di2 * self1.w + bc1.w;

    float h0 = (1.f - 1.f / (1.f + expf(-gz0))) * tanhf(gh0);
    float h1 = (1.f - 1.f / (1.f + expf(-gz1))) * tanhf(gh1);
    float h2 = (1.f - 1.f / (1.f + expf(-gz2))) * tanhf(gh2);
    float h3 = (1.f - 1.f / (1.f + expf(-gz3))) * tanhf(gh3);

    *(float2*)(hout + (size_t)n * 128 + 2 * lane)      = make_float2(h0, h1);
    *(float2*)(hout + (size_t)n * 128 + 64 + 2 * lane) = make_float2(h2, h3);

    float2 w0 = ((const float2*)fcw)[lane];
    float2 w1 = ((const float2*)fcw)[32 + lane];
    float prod = fmaxf(h0, 0.f) * w0.x + fmaxf(h1, 0.f) * w0.y
               + fmaxf(h2, 0.f) * w1.x + fmaxf(h3, 0.f) * w1.y;
    #pragma unroll
    for (int o = 16; o; o >>= 1) prod += __shfl_xor_sync(0xffffffffu, prod, o);
    if (lane == 0) out[n] = prod + fcb[0];
}

// ---------------- launch ----------------
extern "C" void kernel_launch(void* const* d_in, const int* in_sizes, int n_in,
                              void* d_out, int out_size) {
    const float* x     = (const float*)d_in[0];
    const int*   ei    = (const int*)d_in[1];
    const float* ew    = (const float*)d_in[2];
    const float* fc0_w = (const float*)d_in[3];
    const float* fc0_b = (const float*)d_in[4];
    // d_in[5] = att: softmax over one element == 1.0
    const float* czw   = (const float*)d_in[6];
    const float* czb   = (const float*)d_in[7];
    const float* lzw   = (const float*)d_in[8];
    const float* lzb   = (const float*)d_in[9];
    // d_in[10..13] dead (H0 == 0 kills the R branch)
    const float* chw   = (const float*)d_in[14];
    const float* chb   = (const float*)d_in[15];
    const float* lhw   = (const float*)d_in[16];
    const float* lhb   = (const float*)d_in[17];
    const float* fcw   = (const float*)d_in[18];
    const float* fcb   = (const float*)d_in[19];

    const int* src = ei;
    const int* dst = ei + Ee;

    float* out  = (float*)d_out;
    float* hout = out + Nn;

    const int nb = (Nn + 1023) / 1024;
    const int gM = (Nn + 63) / 64;

    static bool attr_done = false;
    if (!attr_done) {
        cudaFuncSetAttribute(k_gemm_fused, cudaFuncAttributeMaxDynamicSharedMemorySize, SMEM_BYTES);
        attr_done = true;
    }

    // launch index 3 = fused fp16 GEMM (ncu capture slot)
    k_prep_x<<<(Nn * FIN / 2 + 255) / 256, 256>>>(x);
    k_prep_b0<<<(FIN * 256 + 255) / 256, 256>>>(fc0_w);
    k_build_wc<<<256, 128>>>(czw, chw, lzw, lhw);

    k_gemm_fused<<<gM, 256, SMEM_BYTES>>>(fc0_b, Nn);   // index 3

    k_build_bc<<<1, 128>>>(czb, chb, lzw, lhw, lzb, lhb);
    k_init<<<(Nn + 255) / 256, 256>>>();
    k_edge_accum<<<(Ee + 255) / 256, 256>>>(dst, ew);
    k_dinv<<<(Nn + 255) / 256, 256>>>();
    k_scan_block<<<nb, 1024>>>();
    k_scan_sums<<<1, 32>>>(nb);
    k_scan_add<<<nb, 1024>>>();
    k_fill<<<(Ee + 255) / 256, 256>>>(src, dst, ew);

    k_agg_gru<<<(Nn + 7) / 8, 256>>>(fcw, fcb, hout, out);
}

// round 10
// speedup vs baseline: 1.3041x; 1.2068x over previous
#include <cuda_runtime.h>
#include <cuda_fp16.h>
#include <math.h>
#include <stdint.h>

#define Nn 100000
#define Ee 800000
#define FIN 128
#define H1  256
#define OUTD 128

// ---------------- scratch (static device globals) ----------------
__device__ __half g_Gh[(size_t)Nn * H1];   // gates pre-aggregation [N,256] fp16
__device__ __half g_Xh[(size_t)Nn * FIN];  // fp16 x
__device__ float  g_deg[Nn];
__device__ float  g_dinv[Nn];
__device__ int    g_count[Nn];
__device__ int    g_rowptr[Nn];
__device__ int    g_cursor[Nn];
__device__ int2   g_csr[Ee];               // {src, __float_as_int(dinv[src]*w)}
__device__ __half g_Wch[H1 * 256];         // folded weights [n][k] fp16, n interleaved (z,h)
__device__ float  g_bc[256];               // folded bias, interleaved
__device__ __half g_Wb0h[256 * FIN];       // fc0_w transposed [n][k] fp16
__device__ int    g_bsums[128];

// ---------------- helpers ----------------
__device__ __forceinline__ void mma_f16(float* c, const uint32_t* a, const uint32_t* b) {
    asm volatile(
        "mma.sync.aligned.m16n8k16.row.col.f32.f16.f16.f32 "
        "{%0,%1,%2,%3},{%4,%5,%6,%7},{%8,%9},{%0,%1,%2,%3};\n"
        : "+f"(c[0]), "+f"(c[1]), "+f"(c[2]), "+f"(c[3])
        : "r"(a[0]), "r"(a[1]), "r"(a[2]), "r"(a[3]), "r"(b[0]), "r"(b[1]));
}

__device__ __forceinline__ uint32_t smem_u32(const void* p) {
    uint32_t a;
    asm("{ .reg .u64 t; cvta.to.shared.u64 t, %1; cvt.u32.u64 %0, t; }" : "=r"(a) : "l"(p));
    return a;
}

__device__ __forceinline__ void cp_async16(uint32_t dst, const void* src, int szbytes) {
    asm volatile("cp.async.cg.shared.global [%0], [%1], 16, %2;\n"
                 :: "r"(dst), "l"(src), "r"(szbytes));
}
#define CP_COMMIT() asm volatile("cp.async.commit_group;\n" ::: "memory")
#define CP_WAIT1()  asm volatile("cp.async.wait_group 1;\n" ::: "memory")

// ---------------- graph prep ----------------
__global__ void k_init() {
    int i = blockIdx.x * blockDim.x + threadIdx.x;
    if (i < Nn) { g_deg[i] = 1.0f; g_count[i] = 0; g_cursor[i] = 0; }
}

__global__ void k_edge_accum(const int* __restrict__ dst, const float* __restrict__ ew) {
    int e = blockIdx.x * blockDim.x + threadIdx.x;
    if (e < Ee) {
        int d = dst[e];
        atomicAdd(&g_deg[d], ew[e]);
        atomicAdd(&g_count[d], 1);
    }
}

__global__ void k_dinv() {
    int i = blockIdx.x * blockDim.x + threadIdx.x;
    if (i < Nn) g_dinv[i] = rsqrtf(g_deg[i]);
}

__global__ void k_scan_block() {
    __shared__ int s[1024];
    int i = blockIdx.x * 1024 + threadIdx.x;
    int v = (i < Nn) ? g_count[i] : 0;
    s[threadIdx.x] = v;
    __syncthreads();
    #pragma unroll
    for (int off = 1; off < 1024; off <<= 1) {
        int t = (threadIdx.x >= off) ? s[threadIdx.x - off] : 0;
        __syncthreads();
        s[threadIdx.x] += t;
        __syncthreads();
    }
    if (i < Nn) g_rowptr[i] = s[threadIdx.x] - v;
    if (threadIdx.x == 1023) g_bsums[blockIdx.x] = s[1023];
}

__global__ void k_scan_sums(int nb) {
    if (threadIdx.x == 0 && blockIdx.x == 0) {
        int acc = 0;
        for (int b = 0; b < nb; b++) { int t = g_bsums[b]; g_bsums[b] = acc; acc += t; }
    }
}

__global__ void k_scan_add() {
    int i = blockIdx.x * 1024 + threadIdx.x;
    if (i < Nn) g_rowptr[i] += g_bsums[blockIdx.x];
}

__global__ void k_fill(const int* __restrict__ src, const int* __restrict__ dst,
                       const float* __restrict__ ew) {
    int e = blockIdx.x * blockDim.x + threadIdx.x;
    if (e < Ee) {
        int d = dst[e], s = src[e];
        int pos = g_rowptr[d] + atomicAdd(&g_cursor[d], 1);
        g_csr[pos] = make_int2(s, __float_as_int(g_dinv[s] * ew[e]));
    }
}

// ---------------- input / weight prep ----------------
__global__ void k_prep_x(const float* __restrict__ x) {
    int i = blockIdx.x * blockDim.x + threadIdx.x;
    if (i < Nn * FIN / 2) {
        float2 v = ((const float2*)x)[i];
        ((__half2*)g_Xh)[i] = __floats2half2_rn(v.x, v.y);
    }
}

// g_Wb0h[n][k] = fp16(fc0_w[k][n])   (fc0_w is [128 k][256 n] row-major)
__global__ void k_prep_b0(const float* __restrict__ w) {
    int i = blockIdx.x * blockDim.x + threadIdx.x;
    if (i < FIN * 256) {
        int n = i >> 7, k = i & 127;
        g_Wb0h[n * FIN + k] = __float2half_rn(w[k * 256 + n]);
    }
}

// g_Wch[n][k], n interleaved (2j=z, 2j+1=h)
__global__ void k_build_wc(const float* __restrict__ czw, const float* __restrict__ chw,
                           const float* __restrict__ lzw, const float* __restrict__ lhw) {
    __shared__ float rz[128], rh[128];
    int k = blockIdx.x;        // 0..255
    int j = threadIdx.x;       // 0..127
    rz[j] = czw[k * 128 + j];
    rh[j] = chw[k * 128 + j];
    __syncthreads();
    float az = 0.f, ah = 0.f;
    #pragma unroll 4
    for (int t = 0; t < 128; t++) {
        az += rz[t] * lzw[t * 128 + j];
        ah += rh[t] * lhw[t * 128 + j];
    }
    g_Wch[(2 * j)     * 256 + k] = __float2half_rn(az);
    g_Wch[(2 * j + 1) * 256 + k] = __float2half_rn(ah);
}

__global__ void k_build_bc(const float* __restrict__ czb, const float* __restrict__ chb,
                           const float* __restrict__ lzw, const float* __restrict__ lhw,
                           const float* __restrict__ lzb, const float* __restrict__ lhb) {
    int j = threadIdx.x;
    float az = lzb[j], ah = lhb[j];
    #pragma unroll 4
    for (int t = 0; t < 128; t++) {
        az += czb[t] * lzw[t * 128 + j];
        ah += chb[t] * lhw[t * 128 + j];
    }
    g_bc[2 * j]     = az;
    g_bc[2 * j + 1] = ah;
}

// ---------------- fused double-GEMM (fp16): G = relu(x@W0+b) @ Wc ----------------
// BM=64, BN=256, 8 warps (warp tile 32x64), mma.m16n8k16.f16, fp32 accum.
#define ASA_B   0
#define ASA_SZB 5120
#define BSA_B   10240
#define BSA_SZB 20480
#define AS2_B   0
#define LDA  40
#define LDB  40
#define LDA2 264
#define BSB_B   51200
#define BSB_SZB 20480
#define SMEM_BYTES 92160

__global__ __launch_bounds__(256, 2) void k_gemm_fused(const float* __restrict__ bias0,
                                                       int M) {
    extern __shared__ char sm[];
    const __half* smh = (const __half*)sm;
    const uint32_t smb = smem_u32(sm);

    const int tid  = threadIdx.x;
    const int lane = tid & 31;
    const int w    = tid >> 5;
    const int wy   = w & 1;
    const int wx   = w >> 1;
    const int g    = lane >> 2;
    const int cq   = lane & 3;

    const int row0  = blockIdx.x * 64;
    const int woffm = wy * 32;
    const int woffn = wx * 64;

    float acc[2][8][4];
    #pragma unroll
    for (int mt = 0; mt < 2; mt++)
        #pragma unroll
        for (int nt = 0; nt < 8; nt++)
            #pragma unroll
            for (int i = 0; i < 4; i++) acc[mt][nt][i] = 0.f;

    auto load_a = [&](int st, int kb) {
        {
            int r = tid >> 2, q = tid & 3;
            int gr = row0 + r;
            int ok = (gr < M);
            const __half* gp = g_Xh + (size_t)(ok ? gr : (M - 1)) * FIN + kb + q * 8;
            cp_async16(smb + ASA_B + st * ASA_SZB + (uint32_t)(r * LDA + q * 8) * 2u,
                       gp, ok ? 16 : 0);
        }
        #pragma unroll
        for (int l = 0; l < 4; l++) {
            int idx = tid + l * 256;
            int n = idx >> 2, q = idx & 3;
            cp_async16(smb + BSA_B + st * BSA_SZB + (uint32_t)(n * LDB + q * 8) * 2u,
                       g_Wb0h + (size_t)n * FIN + kb + q * 8, 16);
        }
    };

    load_a(0, 0);
    CP_COMMIT();

    for (int kbi = 0; kbi < 4; kbi++) {
        if (kbi + 1 < 4) load_a((kbi + 1) & 1, (kbi + 1) * 32);
        CP_COMMIT();
        CP_WAIT1();
        __syncthreads();
        const __half* as = smh + (ASA_B + (kbi & 1) * ASA_SZB) / 2;
        const __half* bs = smh + (BSA_B + (kbi & 1) * BSA_SZB) / 2;

        #pragma unroll
        for (int kk = 0; kk < 32; kk += 16) {
            uint32_t af[2][4], bf[8][2];
            #pragma unroll
            for (int mt = 0; mt < 2; mt++) {
                int mb = woffm + mt * 16;
                af[mt][0] = *(const uint32_t*)(as + (mb + g)     * LDA + kk + 2 * cq);
                af[mt][1] = *(const uint32_t*)(as + (mb + g + 8) * LDA + kk + 2 * cq);
                af[mt][2] = *(const uint32_t*)(as + (mb + g)     * LDA + kk + 2 * cq + 8);
                af[mt][3] = *(const uint32_t*)(as + (mb + g + 8) * LDA + kk + 2 * cq + 8);
            }
            #pragma unroll
            for (int nt = 0; nt < 8; nt++) {
                int n = woffn + nt * 8 + g;
                bf[nt][0] = *(const uint32_t*)(bs + n * LDB + kk + 2 * cq);
                bf[nt][1] = *(const uint32_t*)(bs + n * LDB + kk + 2 * cq + 8);
            }
            #pragma unroll
            for (int mt = 0; mt < 2; mt++)
                #pragma unroll
                for (int nt = 0; nt < 8; nt++)
                    mma_f16(acc[mt][nt], af[mt], bf[nt]);
        }
        __syncthreads();
    }

    // start streaming Wc chunk 0 into Bsb (non-aliased) to overlap with epilogue
    {
        #pragma unroll
        for (int l = 0; l < 4; l++) {
            int idx = tid + l * 256;
            int n = idx >> 2, q = idx & 3;
            cp_async16(smb + BSB_B + (uint32_t)(n * LDB + q * 8) * 2u,
                       g_Wch + (size_t)n * 256 + q * 8, 16);
        }
        CP_COMMIT();
    }

    // stage-A epilogue: relu + bias -> fp16 -> As2 [64][264]
    #pragma unroll
    for (int mt = 0; mt < 2; mt++) {
        int r0 = woffm + mt * 16 + g;
        int r1 = r0 + 8;
        #pragma unroll
        for (int nt = 0; nt < 8; nt++) {
            int col = woffn + nt * 8 + 2 * cq;
            float b0 = bias0[col], b1 = bias0[col + 1];
            __half2 v0 = __floats2half2_rn(fmaxf(acc[mt][nt][0] + b0, 0.f),
                                           fmaxf(acc[mt][nt][1] + b1, 0.f));
            __half2 v1 = __floats2half2_rn(fmaxf(acc[mt][nt][2] + b0, 0.f),
                                           fmaxf(acc[mt][nt][3] + b1, 0.f));
            *(__half2*)(sm + AS2_B + (r0 * LDA2 + col) * 2) = v0;
            *(__half2*)(sm + AS2_B + (r1 * LDA2 + col) * 2) = v1;
        }
    }
    __syncthreads();

    // ---- stage B: G = As2 @ Wct, K=256, 8 chunks of 32 ----
    #pragma unroll
    for (int mt = 0; mt < 2; mt++)
        #pragma unroll
        for (int nt = 0; nt < 8; nt++)
            #pragma unroll
            for (int i = 0; i < 4; i++) acc[mt][nt][i] = 0.f;

    auto load_b = [&](int st, int kc) {
        #pragma unroll
        for (int l = 0; l < 4; l++) {
            int idx = tid + l * 256;
            int n = idx >> 2, q = idx & 3;
            cp_async16(smb + BSB_B + st * BSB_SZB + (uint32_t)(n * LDB + q * 8) * 2u,
                       g_Wch + (size_t)n * 256 + kc + q * 8, 16);
        }
    };

    const __half* a2 = smh + AS2_B / 2;
    for (int it = 0; it < 8; it++) {
        if (it + 1 < 8) load_b((it + 1) & 1, (it + 1) * 32);
        CP_COMMIT();
        CP_WAIT1();
        __syncthreads();
        const __half* bs = smh + (BSB_B + (it & 1) * BSB_SZB) / 2;
        const int kg = it * 32;

        #pragma unroll
        for (int kk = 0; kk < 32; kk += 16) {
            uint32_t af[2][4], bf[8][2];
            #pragma unroll
            for (int mt = 0; mt < 2; mt++) {
                int mb = woffm + mt * 16;
                af[mt][0] = *(const uint32_t*)(a2 + (mb + g)     * LDA2 + kg + kk + 2 * cq);
                af[mt][1] = *(const uint32_t*)(a2 + (mb + g + 8) * LDA2 + kg + kk + 2 * cq);
                af[mt][2] = *(const uint32_t*)(a2 + (mb + g)     * LDA2 + kg + kk + 2 * cq + 8);
                af[mt][3] = *(const uint32_t*)(a2 + (mb + g + 8) * LDA2 + kg + kk + 2 * cq + 8);
            }
            #pragma unroll
            for (int nt = 0; nt < 8; nt++) {
                int n = woffn + nt * 8 + g;
                bf[nt][0] = *(const uint32_t*)(bs + n * LDB + kk + 2 * cq);
                bf[nt][1] = *(const uint32_t*)(bs + n * LDB + kk + 2 * cq + 8);
            }
            #pragma unroll
            for (int mt = 0; mt < 2; mt++)
                #pragma unroll
                for (int nt = 0; nt < 8; nt++)
                    mma_f16(acc[mt][nt], af[mt], bf[nt]);
        }
        __syncthreads();
    }

    // stage-B epilogue: fp16 gates to g_Gh (guarded)
    #pragma unroll
    for (int mt = 0; mt < 2; mt++) {
        int r0 = row0 + woffm + mt * 16 + g;
        int r1 = r0 + 8;
        #pragma unroll
        for (int nt = 0; nt < 8; nt++) {
            int col = woffn + nt * 8 + 2 * cq;
            if (r0 < M)
                *(__half2*)(g_Gh + (size_t)r0 * 256 + col) =
                    __floats2half2_rn(acc[mt][nt][0], acc[mt][nt][1]);
            if (r1 < M)
                *(__half2*)(g_Gh + (size_t)r1 * 256 + col) =
                    __floats2half2_rn(acc[mt][nt][2], acc[mt][nt][3]);
        }
    }
}

// ---------------- fused aggregate + bias + GRU + output head (warp-per-node, fp16 G) ----------------
// Row = 256 halves = 512 B -> exactly one LDG.128 per lane per edge.
__device__ __forceinline__ void acc8(float* a, uint4 u, float c) {
    float2 f0 = __half22float2(*(__half2*)&u.x);
    float2 f1 = __half22float2(*((__half2*)&u.x + 1));
    float2 f2 = __half22float2(*(__half2*)&u.z);
    float2 f3 = __half22float2(*((__half2*)&u.z + 1));
    a[0] += c * f0.x; a[1] += c * f0.y;
    a[2] += c * f1.x; a[3] += c * f1.y;
    a[4] += c * f2.x; a[5] += c * f2.y;
    a[6] += c * f3.x; a[7] += c * f3.y;
}

__global__ __launch_bounds__(256) void k_agg_gru(const float* __restrict__ fcw,
                                                 const float* __restrict__ fcb,
                                                 float* __restrict__ hout,
                                                 float* __restrict__ out) {
    const int wid  = threadIdx.x >> 5;
    const int lane = threadIdx.x & 31;
    const int n    = blockIdx.x * 8 + wid;
    if (n >= Nn) return;

    const uint4* G16 = (const uint4*)g_Gh;     // row stride 32 uint4

    float a[8];
    #pragma unroll
    for (int j = 0; j < 8; j++) a[j] = 0.f;

    const int beg = g_rowptr[n];
    const int count = g_count[n];
    const int nf = count < 32 ? count : 32;

    int2 my = make_int2(0, 0);
    if (lane < nf) my = g_csr[beg + lane];

    int e = 0;
    for (; e + 4 <= nf; e += 4) {
        int s0 = __shfl_sync(0xffffffffu, my.x, e);
        int s1 = __shfl_sync(0xffffffffu, my.x, e + 1);
        int s2 = __shfl_sync(0xffffffffu, my.x, e + 2);
        int s3 = __shfl_sync(0xffffffffu, my.x, e + 3);
        float c0 = __int_as_float(__shfl_sync(0xffffffffu, my.y, e));
        float c1 = __int_as_float(__shfl_sync(0xffffffffu, my.y, e + 1));
        float c2 = __int_as_float(__shfl_sync(0xffffffffu, my.y, e + 2));
        float c3 = __int_as_float(__shfl_sync(0xffffffffu, my.y, e + 3));
        uint4 u0 = G16[(size_t)s0 * 32 + lane];
        uint4 u1 = G16[(size_t)s1 * 32 + lane];
        uint4 u2 = G16[(size_t)s2 * 32 + lane];
        uint4 u3 = G16[(size_t)s3 * 32 + lane];
        acc8(a, u0, c0); acc8(a, u1, c1); acc8(a, u2, c2); acc8(a, u3, c3);
    }
    for (; e < nf; e++) {
        int   s = __shfl_sync(0xffffffffu, my.x, e);
        float c = __int_as_float(__shfl_sync(0xffffffffu, my.y, e));
        acc8(a, G16[(size_t)s * 32 + lane], c);
    }
    for (int ee = 32; ee < count; ee++) {      // ~never taken (Poisson(8))
        int2 p = g_csr[beg + ee];
        acc8(a, G16[(size_t)p.x * 32 + lane], __int_as_float(p.y));
    }

    const float di  = g_dinv[n];
    const float di2 = di * di;
    float s[8];
    {
        uint4 us = G16[(size_t)n * 32 + lane];
        float2 f0 = __half22float2(*(__half2*)&us.x);
        float2 f1 = __half22float2(*((__half2*)&us.x + 1));
        float2 f2 = __half22float2(*(__half2*)&us.z);
        float2 f3 = __half22float2(*((__half2*)&us.z + 1));
        s[0] = f0.x; s[1] = f0.y; s[2] = f1.x; s[3] = f1.y;
        s[4] = f2.x; s[5] = f2.y; s[6] = f3.x; s[7] = f3.y;
    }
    float4 bc0 = ((const float4*)g_bc)[2 * lane];
    float4 bc1 = ((const float4*)g_bc)[2 * lane + 1];
    float gate[8];
    gate[0] = a[0] * di + di2 * s[0] + bc0.x;
    gate[1] = a[1] * di + di2 * s[1] + bc0.y;
    gate[2] = a[2] * di + di2 * s[2] + bc0.z;
    gate[3] = a[3] * di + di2 * s[3] + bc0.w;
    gate[4] = a[4] * di + di2 * s[4] + bc1.x;
    gate[5] = a[5] * di + di2 * s[5] + bc1.y;
    gate[6] = a[6] * di + di2 * s[6] + bc1.z;
    gate[7] = a[7] * di + di2 * s[7] + bc1.w;

    float h[4];
    #pragma unroll
    for (int i = 0; i < 4; i++) {
        float z = 1.f / (1.f + expf(-gate[2 * i]));
        h[i] = (1.f - z) * tanhf(gate[2 * i + 1]);
    }

    *(float4*)(hout + (size_t)n * 128 + 4 * lane) = make_float4(h[0], h[1], h[2], h[3]);

    float4 wv = ((const float4*)fcw)[lane];
    float prod = fmaxf(h[0], 0.f) * wv.x + fmaxf(h[1], 0.f) * wv.y
               + fmaxf(h[2], 0.f) * wv.z + fmaxf(h[3], 0.f) * wv.w;
    #pragma unroll
    for (int o = 16; o; o >>= 1) prod += __shfl_xor_sync(0xffffffffu, prod, o);
    if (lane == 0) out[n] = prod + fcb[0];
}

// ---------------- launch ----------------
extern "C" void kernel_launch(void* const* d_in, const int* in_sizes, int n_in,
                              void* d_out, int out_size) {
    const float* x     = (const float*)d_in[0];
    const int*   ei    = (const int*)d_in[1];
    const float* ew    = (const float*)d_in[2];
    const float* fc0_w = (const float*)d_in[3];
    const float* fc0_b = (const float*)d_in[4];
    // d_in[5] = att: softmax over one element == 1.0
    const float* czw   = (const float*)d_in[6];
    const float* czb   = (const float*)d_in[7];
    const float* lzw   = (const float*)d_in[8];
    const float* lzb   = (const float*)d_in[9];
    // d_in[10..13] dead (H0 == 0 kills the R branch)
    const float* chw   = (const float*)d_in[14];
    const float* chb   = (const float*)d_in[15];
    const float* lhw   = (const float*)d_in[16];
    const float* lhb   = (const float*)d_in[17];
    const float* fcw   = (const float*)d_in[18];
    const float* fcb   = (const float*)d_in[19];

    const int* src = ei;
    const int* dst = ei + Ee;

    float* out  = (float*)d_out;
    float* hout = out + Nn;

    const int nb = (Nn + 1023) / 1024;
    const int gM = (Nn + 63) / 64;

    static bool attr_done = false;
    if (!attr_done) {
        cudaFuncSetAttribute(k_gemm_fused, cudaFuncAttributeMaxDynamicSharedMemorySize, SMEM_BYTES);
        attr_done = true;
    }

    // launch index 3 = fused fp16 GEMM (ncu capture slot)
    k_prep_x<<<(Nn * FIN / 2 + 255) / 256, 256>>>(x);
    k_prep_b0<<<(FIN * 256 + 255) / 256, 256>>>(fc0_w);
    k_build_wc<<<256, 128>>>(czw, chw, lzw, lhw);

    k_gemm_fused<<<gM, 256, SMEM_BYTES>>>(fc0_b, Nn);   // index 3

    k_build_bc<<<1, 128>>>(czb, chb, lzw, lhw, lzb, lhb);
    k_init<<<(Nn + 255) / 256, 256>>>();
    k_edge_accum<<<(Ee + 255) / 256, 256>>>(dst, ew);
    k_dinv<<<(Nn + 255) / 256, 256>>>();
    k_scan_block<<<nb, 1024>>>();
    k_scan_sums<<<1, 32>>>(nb);
    k_scan_add<<<nb, 1024>>>();
    k_fill<<<(Ee + 255) / 256, 256>>>(src, dst, ew);

    k_agg_gru<<<(Nn + 7) / 8, 256>>>(fcw, fcb, hout, out);
}

// round 11
// speedup vs baseline: 1.3642x; 1.0461x over previous
#include <cuda_runtime.h>
#include <cuda_fp16.h>
#include <math.h>
#include <stdint.h>

#define Nn 100000
#define Ee 800000
#define FIN 128
#define H1  256
#define OUTD 128

// ---------------- scratch (static device globals) ----------------
__device__ __half g_Gh[(size_t)Nn * H1];   // gates pre-aggregation [N,256] fp16
__device__ __half g_Xh[(size_t)Nn * FIN];  // fp16 x
__device__ float  g_deg[Nn];
__device__ float  g_dinv[Nn];
__device__ int    g_count[Nn];
__device__ int    g_rowptr[Nn];
__device__ int    g_cursor[Nn];
__device__ int2   g_csr[Ee];               // {src, __float_as_int(dinv[src]*w)}
__device__ __half g_Wch[H1 * 256];         // folded weights [n][k] fp16, n interleaved (z,h)
__device__ float  g_bc[256];               // folded bias, interleaved
__device__ __half g_Wb0h[256 * FIN];       // fc0_w transposed [n][k] fp16
__device__ int    g_bsums[128];

// ---------------- helpers ----------------
__device__ __forceinline__ void mma_f16(float* c, const uint32_t* a, const uint32_t* b) {
    asm volatile(
        "mma.sync.aligned.m16n8k16.row.col.f32.f16.f16.f32 "
        "{%0,%1,%2,%3},{%4,%5,%6,%7},{%8,%9},{%0,%1,%2,%3};\n"
        : "+f"(c[0]), "+f"(c[1]), "+f"(c[2]), "+f"(c[3])
        : "r"(a[0]), "r"(a[1]), "r"(a[2]), "r"(a[3]), "r"(b[0]), "r"(b[1]));
}

#define LDSM_X4(r0, r1, r2, r3, addr)                                          \
    asm volatile("ldmatrix.sync.aligned.m8n8.x4.shared.b16 {%0,%1,%2,%3}, [%4];" \
                 : "=r"(r0), "=r"(r1), "=r"(r2), "=r"(r3) : "r"(addr))

__device__ __forceinline__ uint32_t smem_u32(const void* p) {
    uint32_t a;
    asm("{ .reg .u64 t; cvta.to.shared.u64 t, %1; cvt.u32.u64 %0, t; }" : "=r"(a) : "l"(p));
    return a;
}

__device__ __forceinline__ void cp_async16(uint32_t dst, const void* src, int szbytes) {
    asm volatile("cp.async.cg.shared.global [%0], [%1], 16, %2;\n"
                 :: "r"(dst), "l"(src), "r"(szbytes));
}
#define CP_COMMIT() asm volatile("cp.async.commit_group;\n" ::: "memory")
#define CP_WAIT1()  asm volatile("cp.async.wait_group 1;\n" ::: "memory")

// ---------------- graph prep ----------------
__global__ void k_init() {
    int i = blockIdx.x * blockDim.x + threadIdx.x;
    if (i < Nn) { g_deg[i] = 1.0f; g_count[i] = 0; g_cursor[i] = 0; }
}

__global__ void k_edge_accum(const int* __restrict__ dst, const float* __restrict__ ew) {
    int e = blockIdx.x * blockDim.x + threadIdx.x;
    if (e < Ee) {
        int d = dst[e];
        atomicAdd(&g_deg[d], ew[e]);
        atomicAdd(&g_count[d], 1);
    }
}

__global__ void k_dinv() {
    int i = blockIdx.x * blockDim.x + threadIdx.x;
    if (i < Nn) g_dinv[i] = rsqrtf(g_deg[i]);
}

__global__ void k_scan_block() {
    __shared__ int s[1024];
    int i = blockIdx.x * 1024 + threadIdx.x;
    int v = (i < Nn) ? g_count[i] : 0;
    s[threadIdx.x] = v;
    __syncthreads();
    #pragma unroll
    for (int off = 1; off < 1024; off <<= 1) {
        int t = (threadIdx.x >= off) ? s[threadIdx.x - off] : 0;
        __syncthreads();
        s[threadIdx.x] += t;
        __syncthreads();
    }
    if (i < Nn) g_rowptr[i] = s[threadIdx.x] - v;
    if (threadIdx.x == 1023) g_bsums[blockIdx.x] = s[1023];
}

__global__ void k_scan_sums(int nb) {
    if (threadIdx.x == 0 && blockIdx.x == 0) {
        int acc = 0;
        for (int b = 0; b < nb; b++) { int t = g_bsums[b]; g_bsums[b] = acc; acc += t; }
    }
}

__global__ void k_scan_add() {
    int i = blockIdx.x * 1024 + threadIdx.x;
    if (i < Nn) g_rowptr[i] += g_bsums[blockIdx.x];
}

__global__ void k_fill(const int* __restrict__ src, const int* __restrict__ dst,
                       const float* __restrict__ ew) {
    int e = blockIdx.x * blockDim.x + threadIdx.x;
    if (e < Ee) {
        int d = dst[e], s = src[e];
        int pos = g_rowptr[d] + atomicAdd(&g_cursor[d], 1);
        g_csr[pos] = make_int2(s, __float_as_int(g_dinv[s] * ew[e]));
    }
}

// ---------------- input / weight prep ----------------
__global__ void k_prep_x(const float* __restrict__ x) {
    int i = blockIdx.x * blockDim.x + threadIdx.x;
    if (i < Nn * FIN / 2) {
        float2 v = ((const float2*)x)[i];
        ((__half2*)g_Xh)[i] = __floats2half2_rn(v.x, v.y);
    }
}

// g_Wb0h[n][k] = fp16(fc0_w[k][n])   (fc0_w is [128 k][256 n] row-major)
__global__ void k_prep_b0(const float* __restrict__ w) {
    int i = blockIdx.x * blockDim.x + threadIdx.x;
    if (i < FIN * 256) {
        int n = i >> 7, k = i & 127;
        g_Wb0h[n * FIN + k] = __float2half_rn(w[k * 256 + n]);
    }
}

// g_Wch[n][k], n interleaved (2j=z, 2j+1=h)
__global__ void k_build_wc(const float* __restrict__ czw, const float* __restrict__ chw,
                           const float* __restrict__ lzw, const float* __restrict__ lhw) {
    __shared__ float rz[128], rh[128];
    int k = blockIdx.x;        // 0..255
    int j = threadIdx.x;       // 0..127
    rz[j] = czw[k * 128 + j];
    rh[j] = chw[k * 128 + j];
    __syncthreads();
    float az = 0.f, ah = 0.f;
    #pragma unroll 4
    for (int t = 0; t < 128; t++) {
        az += rz[t] * lzw[t * 128 + j];
        ah += rh[t] * lhw[t * 128 + j];
    }
    g_Wch[(2 * j)     * 256 + k] = __float2half_rn(az);
    g_Wch[(2 * j + 1) * 256 + k] = __float2half_rn(ah);
}

__global__ void k_build_bc(const float* __restrict__ czb, const float* __restrict__ chb,
                           const float* __restrict__ lzw, const float* __restrict__ lhw,
                           const float* __restrict__ lzb, const float* __restrict__ lhb) {
    int j = threadIdx.x;
    float az = lzb[j], ah = lhb[j];
    #pragma unroll 4
    for (int t = 0; t < 128; t++) {
        az += czb[t] * lzw[t * 128 + j];
        ah += chb[t] * lhw[t * 128 + j];
    }
    g_bc[2 * j]     = az;
    g_bc[2 * j + 1] = ah;
}

// ---------------- fused double-GEMM (fp16, ldmatrix): G = relu(x@W0+b) @ Wc ----------------
// BM=64, BN=256, 8 warps (warp tile 32x64), mma.m16n8k16.f16, fp32 accum.
// Fragment loads via ldmatrix.m8n8.x4: A = 2/step, B = 4/step (vs 24 scalar LDS).
#define ASA_B   0
#define ASA_SZB 5120
#define BSA_B   10240
#define BSA_SZB 20480
#define AS2_B   0
#define LDA  40
#define LDB  40
#define LDA2 264
#define BSB_B   51200
#define BSB_SZB 20480
#define SMEM_BYTES 92160

__global__ __launch_bounds__(256, 2) void k_gemm_fused(const float* __restrict__ bias0,
                                                       int M) {
    extern __shared__ char sm[];
    const uint32_t smb = smem_u32(sm);

    const int tid  = threadIdx.x;
    const int lane = tid & 31;
    const int w    = tid >> 5;
    const int wy   = w & 1;
    const int wx   = w >> 1;
    const int g    = lane >> 2;
    const int cq   = lane & 3;

    const int row0  = blockIdx.x * 64;
    const int woffm = wy * 32;
    const int woffn = wx * 64;

    // ldmatrix lane -> source row/col offsets
    const uint32_t lrow_a = ((lane >> 3) & 1) * 8 + (lane & 7);   // A: row within 16-tile
    const uint32_t lk_a   = (lane >> 4) * 8;                      // A: k offset
    const uint32_t lrow_b = (lane >> 4) * 8 + (lane & 7);         // B: n within 16-pair
    const uint32_t lk_b   = ((lane >> 3) & 1) * 8;                // B: k offset

    float acc[2][8][4];
    #pragma unroll
    for (int mt = 0; mt < 2; mt++)
        #pragma unroll
        for (int nt = 0; nt < 8; nt++)
            #pragma unroll
            for (int i = 0; i < 4; i++) acc[mt][nt][i] = 0.f;

    auto load_a = [&](int st, int kb) {
        {
            int r = tid >> 2, q = tid & 3;
            int gr = row0 + r;
            int ok = (gr < M);
            const __half* gp = g_Xh + (size_t)(ok ? gr : (M - 1)) * FIN + kb + q * 8;
            cp_async16(smb + ASA_B + st * ASA_SZB + (uint32_t)(r * LDA + q * 8) * 2u,
                       gp, ok ? 16 : 0);
        }
        #pragma unroll
        for (int l = 0; l < 4; l++) {
            int idx = tid + l * 256;
            int n = idx >> 2, q = idx & 3;
            cp_async16(smb + BSA_B + st * BSA_SZB + (uint32_t)(n * LDB + q * 8) * 2u,
                       g_Wb0h + (size_t)n * FIN + kb + q * 8, 16);
        }
    };

    load_a(0, 0);
    CP_COMMIT();

    for (int kbi = 0; kbi < 4; kbi++) {
        if (kbi + 1 < 4) load_a((kbi + 1) & 1, (kbi + 1) * 32);
        CP_COMMIT();
        CP_WAIT1();
        __syncthreads();
        const uint32_t abase = smb + ASA_B + (kbi & 1) * ASA_SZB
                             + ((woffm + lrow_a) * LDA + lk_a) * 2u;
        const uint32_t bbase = smb + BSA_B + (kbi & 1) * BSA_SZB
                             + ((woffn + lrow_b) * LDB + lk_b) * 2u;

        #pragma unroll
        for (int kk = 0; kk < 32; kk += 16) {
            uint32_t af[2][4], bf[8][2];
            LDSM_X4(af[0][0], af[0][1], af[0][2], af[0][3], abase + kk * 2u);
            LDSM_X4(af[1][0], af[1][1], af[1][2], af[1][3],
                    abase + (16 * LDA + kk) * 2u);
            #pragma unroll
            for (int p = 0; p < 4; p++)
                LDSM_X4(bf[2 * p][0], bf[2 * p][1], bf[2 * p + 1][0], bf[2 * p + 1][1],
                        bbase + (p * 16 * LDB + kk) * 2u);
            #pragma unroll
            for (int mt = 0; mt < 2; mt++)
                #pragma unroll
                for (int nt = 0; nt < 8; nt++)
                    mma_f16(acc[mt][nt], af[mt], bf[nt]);
        }
        __syncthreads();
    }

    // start streaming Wc chunk 0 into Bsb (non-aliased) to overlap with epilogue
    {
        #pragma unroll
        for (int l = 0; l < 4; l++) {
            int idx = tid + l * 256;
            int n = idx >> 2, q = idx & 3;
            cp_async16(smb + BSB_B + (uint32_t)(n * LDB + q * 8) * 2u,
                       g_Wch + (size_t)n * 256 + q * 8, 16);
        }
        CP_COMMIT();
    }

    // stage-A epilogue: relu + bias -> fp16 -> As2 [64][264]
    #pragma unroll
    for (int mt = 0; mt < 2; mt++) {
        int r0 = woffm + mt * 16 + g;
        int r1 = r0 + 8;
        #pragma unroll
        for (int nt = 0; nt < 8; nt++) {
            int col = woffn + nt * 8 + 2 * cq;
            float b0 = bias0[col], b1 = bias0[col + 1];
            __half2 v0 = __floats2half2_rn(fmaxf(acc[mt][nt][0] + b0, 0.f),
                                           fmaxf(acc[mt][nt][1] + b1, 0.f));
            __half2 v1 = __floats2half2_rn(fmaxf(acc[mt][nt][2] + b0, 0.f),
                                           fmaxf(acc[mt][nt][3] + b1, 0.f));
            *(__half2*)(sm + AS2_B + (r0 * LDA2 + col) * 2) = v0;
            *(__half2*)(sm + AS2_B + (r1 * LDA2 + col) * 2) = v1;
        }
    }
    __syncthreads();

    // ---- stage B: G = As2 @ Wct, K=256, 8 chunks of 32 ----
    #pragma unroll
    for (int mt = 0; mt < 2; mt++)
        #pragma unroll
        for (int nt = 0; nt < 8; nt++)
            #pragma unroll
            for (int i = 0; i < 4; i++) acc[mt][nt][i] = 0.f;

    auto load_b = [&](int st, int kc) {
        #pragma unroll
        for (int l = 0; l < 4; l++) {
            int idx = tid + l * 256;
            int n = idx >> 2, q = idx & 3;
            cp_async16(smb + BSB_B + st * BSB_SZB + (uint32_t)(n * LDB + q * 8) * 2u,
                       g_Wch + (size_t)n * 256 + kc + q * 8, 16);
        }
    };

    const uint32_t a2base = smb + AS2_B + ((woffm + lrow_a) * LDA2 + lk_a) * 2u;
    for (int it = 0; it < 8; it++) {
        if (it + 1 < 8) load_b((it + 1) & 1, (it + 1) * 32);
        CP_COMMIT();
        CP_WAIT1();
        __syncthreads();
        const uint32_t bbase = smb + BSB_B + (it & 1) * BSB_SZB
                             + ((woffn + lrow_b) * LDB + lk_b) * 2u;
        const int kg = it * 32;

        #pragma unroll
        for (int kk = 0; kk < 32; kk += 16) {
            uint32_t af[2][4], bf[8][2];
            LDSM_X4(af[0][0], af[0][1], af[0][2], af[0][3], a2base + (kg + kk) * 2u);
            LDSM_X4(af[1][0], af[1][1], af[1][2], af[1][3],
                    a2base + (16 * LDA2 + kg + kk) * 2u);
            #pragma unroll
            for (int p = 0; p < 4; p++)
                LDSM_X4(bf[2 * p][0], bf[2 * p][1], bf[2 * p + 1][0], bf[2 * p + 1][1],
                        bbase + (p * 16 * LDB + kk) * 2u);
            #pragma unroll
            for (int mt = 0; mt < 2; mt++)
                #pragma unroll
                for (int nt = 0; nt < 8; nt++)
                    mma_f16(acc[mt][nt], af[mt], bf[nt]);
        }
        __syncthreads();
    }

    // stage-B epilogue: fp16 gates to g_Gh (guarded)
    #pragma unroll
    for (int mt = 0; mt < 2; mt++) {
        int r0 = row0 + woffm + mt * 16 + g;
        int r1 = r0 + 8;
        #pragma unroll
        for (int nt = 0; nt < 8; nt++) {
            int col = woffn + nt * 8 + 2 * cq;
            if (r0 < M)
                *(__half2*)(g_Gh + (size_t)r0 * 256 + col) =
                    __floats2half2_rn(acc[mt][nt][0], acc[mt][nt][1]);
            if (r1 < M)
                *(__half2*)(g_Gh + (size_t)r1 * 256 + col) =
                    __floats2half2_rn(acc[mt][nt][2], acc[mt][nt][3]);
        }
    }
}

// ---------------- fused aggregate + bias + GRU + output head (warp-per-node, fp16 G) ----------------
__device__ __forceinline__ void acc8(float* a, uint4 u, float c) {
    float2 f0 = __half22float2(*(__half2*)&u.x);
    float2 f1 = __half22float2(*((__half2*)&u.x + 1));
    float2 f2 = __half22float2(*(__half2*)&u.z);
    float2 f3 = __half22float2(*((__half2*)&u.z + 1));
    a[0] += c * f0.x; a[1] += c * f0.y;
    a[2] += c * f1.x; a[3] += c * f1.y;
    a[4] += c * f2.x; a[5] += c * f2.y;
    a[6] += c * f3.x; a[7] += c * f3.y;
}

__global__ __launch_bounds__(256) void k_agg_gru(const float* __restrict__ fcw,
                                                 const float* __restrict__ fcb,
                                                 float* __restrict__ hout,
                                                 float* __restrict__ out) {
    const int wid  = threadIdx.x >> 5;
    const int lane = threadIdx.x & 31;
    const int n    = blockIdx.x * 8 + wid;
    if (n >= Nn) return;

    const uint4* G16 = (const uint4*)g_Gh;     // row stride 32 uint4

    float a[8];
    #pragma unroll
    for (int j = 0; j < 8; j++) a[j] = 0.f;

    const int beg = g_rowptr[n];
    const int count = g_count[n];
    const int nf = count < 32 ? count : 32;

    int2 my = make_int2(0, 0);
    if (lane < nf) my = g_csr[beg + lane];

    int e = 0;
    for (; e + 4 <= nf; e += 4) {
        int s0 = __shfl_sync(0xffffffffu, my.x, e);
        int s1 = __shfl_sync(0xffffffffu, my.x, e + 1);
        int s2 = __shfl_sync(0xffffffffu, my.x, e + 2);
        int s3 = __shfl_sync(0xffffffffu, my.x, e + 3);
        float c0 = __int_as_float(__shfl_sync(0xffffffffu, my.y, e));
        float c1 = __int_as_float(__shfl_sync(0xffffffffu, my.y, e + 1));
        float c2 = __int_as_float(__shfl_sync(0xffffffffu, my.y, e + 2));
        float c3 = __int_as_float(__shfl_sync(0xffffffffu, my.y, e + 3));
        uint4 u0 = G16[(size_t)s0 * 32 + lane];
        uint4 u1 = G16[(size_t)s1 * 32 + lane];
        uint4 u2 = G16[(size_t)s2 * 32 + lane];
        uint4 u3 = G16[(size_t)s3 * 32 + lane];
        acc8(a, u0, c0); acc8(a, u1, c1); acc8(a, u2, c2); acc8(a, u3, c3);
    }
    for (; e < nf; e++) {
        int   s = __shfl_sync(0xffffffffu, my.x, e);
        float c = __int_as_float(__shfl_sync(0xffffffffu, my.y, e));
        acc8(a, G16[(size_t)s * 32 + lane], c);
    }
    for (int ee = 32; ee < count; ee++) {      // ~never taken (Poisson(8))
        int2 p = g_csr[beg + ee];
        acc8(a, G16[(size_t)p.x * 32 + lane], __int_as_float(p.y));
    }

    const float di  = g_dinv[n];
    const float di2 = di * di;
    float s[8];
    {
        uint4 us = G16[(size_t)n * 32 + lane];
        float2 f0 = __half22float2(*(__half2*)&us.x);
        float2 f1 = __half22float2(*((__half2*)&us.x + 1));
        float2 f2 = __half22float2(*(__half2*)&us.z);
        float2 f3 = __half22float2(*((__half2*)&us.z + 1));
        s[0] = f0.x; s[1] = f0.y; s[2] = f1.x; s[3] = f1.y;
        s[4] = f2.x; s[5] = f2.y; s[6] = f3.x; s[7] = f3.y;
    }
    float4 bc0 = ((const float4*)g_bc)[2 * lane];
    float4 bc1 = ((const float4*)g_bc)[2 * lane + 1];
    float gate[8];
    gate[0] = a[0] * di + di2 * s[0] + bc0.x;
    gate[1] = a[1] * di + di2 * s[1] + bc0.y;
    gate[2] = a[2] * di + di2 * s[2] + bc0.z;
    gate[3] = a[3] * di + di2 * s[3] + bc0.w;
    gate[4] = a[4] * di + di2 * s[4] + bc1.x;
    gate[5] = a[5] * di + di2 * s[5] + bc1.y;
    gate[6] = a[6] * di + di2 * s[6] + bc1.z;
    gate[7] = a[7] * di + di2 * s[7] + bc1.w;

    float h[4];
    #pragma unroll
    for (int i = 0; i < 4; i++) {
        float z = 1.f / (1.f + expf(-gate[2 * i]));
        h[i] = (1.f - z) * tanhf(gate[2 * i + 1]);
    }

    *(float4*)(hout + (size_t)n * 128 + 4 * lane) = make_float4(h[0], h[1], h[2], h[3]);

    float4 wv = ((const float4*)fcw)[lane];
    float prod = fmaxf(h[0], 0.f) * wv.x + fmaxf(h[1], 0.f) * wv.y
               + fmaxf(h[2], 0.f) * wv.z + fmaxf(h[3], 0.f) * wv.w;
    #pragma unroll
    for (int o = 16; o; o >>= 1) prod += __shfl_xor_sync(0xffffffffu, prod, o);
    if (lane == 0) out[n] = prod + fcb[0];
}

// ---------------- launch ----------------
extern "C" void kernel_launch(void* const* d_in, const int* in_sizes, int n_in,
                              void* d_out, int out_size) {
    const float* x     = (const float*)d_in[0];
    const int*   ei    = (const int*)d_in[1];
    const float* ew    = (const float*)d_in[2];
    const float* fc0_w = (const float*)d_in[3];
    const float* fc0_b = (const float*)d_in[4];
    // d_in[5] = att: softmax over one element == 1.0
    const float* czw   = (const float*)d_in[6];
    const float* czb   = (const float*)d_in[7];
    const float* lzw   = (const float*)d_in[8];
    const float* lzb   = (const float*)d_in[9];
    // d_in[10..13] dead (H0 == 0 kills the R branch)
    const float* chw   = (const float*)d_in[14];
    const float* chb   = (const float*)d_in[15];
    const float* lhw   = (const float*)d_in[16];
    const float* lhb   = (const float*)d_in[17];
    const float* fcw   = (const float*)d_in[18];
    const float* fcb   = (const float*)d_in[19];

    const int* src = ei;
    const int* dst = ei + Ee;

    float* out  = (float*)d_out;
    float* hout = out + Nn;

    const int nb = (Nn + 1023) / 1024;
    const int gM = (Nn + 63) / 64;

    static bool attr_done = false;
    if (!attr_done) {
        cudaFuncSetAttribute(k_gemm_fused, cudaFuncAttributeMaxDynamicSharedMemorySize, SMEM_BYTES);
        attr_done = true;
    }

    // launch index 3 = fused fp16 GEMM (ncu capture slot)
    k_prep_x<<<(Nn * FIN / 2 + 255) / 256, 256>>>(x);
    k_prep_b0<<<(FIN * 256 + 255) / 256, 256>>>(fc0_w);
    k_build_wc<<<256, 128>>>(czw, chw, lzw, lhw);

    k_gemm_fused<<<gM, 256, SMEM_BYTES>>>(fc0_b, Nn);   // index 3

    k_build_bc<<<1, 128>>>(czb, chb, lzw, lhw, lzb, lhb);
    k_init<<<(Nn + 255) / 256, 256>>>();
    k_edge_accum<<<(Ee + 255) / 256, 256>>>(dst, ew);
    k_dinv<<<(Nn + 255) / 256, 256>>>();
    k_scan_block<<<nb, 1024>>>();
    k_scan_sums<<<1, 32>>>(nb);
    k_scan_add<<<nb, 1024>>>();
    k_fill<<<(Ee + 255) / 256, 256>>>(src, dst, ew);

    k_agg_gru<<<(Nn + 7) / 8, 256>>>(fcw, fcb, hout, out);
}

// round 12
// speedup vs baseline: 1.5565x; 1.1409x over previous
#include <cuda_runtime.h>
#include <cuda_fp16.h>
#include <math.h>
#include <stdint.h>

#define Nn 100000
#define Ee 800000
#define FIN 128
#define H1  256
#define OUTD 128

// ---------------- scratch (static device globals) ----------------
__device__ __half g_Gh[(size_t)Nn * H1];   // gates pre-aggregation [N,256] fp16
__device__ __half g_Xh[(size_t)Nn * FIN];  // fp16 x
__device__ float  g_deg[Nn];
__device__ float  g_dinv[Nn];
__device__ int    g_count[Nn];
__device__ int    g_rowptr[Nn];
__device__ int    g_cursor[Nn];
__device__ int2   g_csr[Ee];               // {src, __float_as_int(dinv[src]*w)}
__device__ __half g_Wch[H1 * 256];         // folded weights [n][k] fp16, n interleaved (z,h)
__device__ float  g_bc[256];               // folded bias, interleaved
__device__ __half g_Wb0h[256 * FIN];       // fc0_w transposed [n][k] fp16
__device__ int    g_bsums[128];

// ---------------- helpers ----------------
__device__ __forceinline__ void mma_f16(float* c, const uint32_t* a, const uint32_t* b) {
    asm volatile(
        "mma.sync.aligned.m16n8k16.row.col.f32.f16.f16.f32 "
        "{%0,%1,%2,%3},{%4,%5,%6,%7},{%8,%9},{%0,%1,%2,%3};\n"
        : "+f"(c[0]), "+f"(c[1]), "+f"(c[2]), "+f"(c[3])
        : "r"(a[0]), "r"(a[1]), "r"(a[2]), "r"(a[3]), "r"(b[0]), "r"(b[1]));
}

#define LDSM_X4(r0, r1, r2, r3, addr)                                          \
    asm volatile("ldmatrix.sync.aligned.m8n8.x4.shared.b16 {%0,%1,%2,%3}, [%4];" \
                 : "=r"(r0), "=r"(r1), "=r"(r2), "=r"(r3) : "r"(addr))

__device__ __forceinline__ uint32_t smem_u32(const void* p) {
    uint32_t a;
    asm("{ .reg .u64 t; cvta.to.shared.u64 t, %1; cvt.u32.u64 %0, t; }" : "=r"(a) : "l"(p));
    return a;
}

__device__ __forceinline__ void cp_async16(uint32_t dst, const void* src, int szbytes) {
    asm volatile("cp.async.cg.shared.global [%0], [%1], 16, %2;\n"
                 :: "r"(dst), "l"(src), "r"(szbytes));
}
#define CP_COMMIT() asm volatile("cp.async.commit_group;\n" ::: "memory")
#define CP_WAIT1()  asm volatile("cp.async.wait_group 1;\n" ::: "memory")

// ---------------- graph prep ----------------
__global__ void k_init() {
    int i = blockIdx.x * blockDim.x + threadIdx.x;
    if (i < Nn) { g_deg[i] = 1.0f; g_count[i] = 0; g_cursor[i] = 0; }
}

__global__ void k_edge_accum(const int* __restrict__ dst, const float* __restrict__ ew) {
    int e = blockIdx.x * blockDim.x + threadIdx.x;
    if (e < Ee) {
        int d = dst[e];
        atomicAdd(&g_deg[d], ew[e]);
        atomicAdd(&g_count[d], 1);
    }
}

__global__ void k_dinv() {
    int i = blockIdx.x * blockDim.x + threadIdx.x;
    if (i < Nn) g_dinv[i] = rsqrtf(g_deg[i]);
}

__global__ void k_scan_block() {
    __shared__ int s[1024];
    int i = blockIdx.x * 1024 + threadIdx.x;
    int v = (i < Nn) ? g_count[i] : 0;
    s[threadIdx.x] = v;
    __syncthreads();
    #pragma unroll
    for (int off = 1; off < 1024; off <<= 1) {
        int t = (threadIdx.x >= off) ? s[threadIdx.x - off] : 0;
        __syncthreads();
        s[threadIdx.x] += t;
        __syncthreads();
    }
    if (i < Nn) g_rowptr[i] = s[threadIdx.x] - v;
    if (threadIdx.x == 1023) g_bsums[blockIdx.x] = s[1023];
}

__global__ void k_scan_sums(int nb) {
    if (threadIdx.x == 0 && blockIdx.x == 0) {
        int acc = 0;
        for (int b = 0; b < nb; b++) { int t = g_bsums[b]; g_bsums[b] = acc; acc += t; }
    }
}

__global__ void k_scan_add() {
    int i = blockIdx.x * 1024 + threadIdx.x;
    if (i < Nn) g_rowptr[i] += g_bsums[blockIdx.x];
}

__global__ void k_fill(const int* __restrict__ src, const int* __restrict__ dst,
                       const float* __restrict__ ew) {
    int e = blockIdx.x * blockDim.x + threadIdx.x;
    if (e < Ee) {
        int d = dst[e], s = src[e];
        int pos = g_rowptr[d] + atomicAdd(&g_cursor[d], 1);
        g_csr[pos] = make_int2(s, __float_as_int(g_dinv[s] * ew[e]));
    }
}

// ---------------- input / weight prep ----------------
__global__ void k_prep_x(const float* __restrict__ x) {
    int i = blockIdx.x * blockDim.x + threadIdx.x;
    if (i < Nn * FIN / 2) {
        float2 v = ((const float2*)x)[i];
        ((__half2*)g_Xh)[i] = __floats2half2_rn(v.x, v.y);
    }
}

// g_Wb0h[n][k] = fp16(fc0_w[k][n])   (fc0_w is [128 k][256 n] row-major)
__global__ void k_prep_b0(const float* __restrict__ w) {
    int i = blockIdx.x * blockDim.x + threadIdx.x;
    if (i < FIN * 256) {
        int n = i >> 7, k = i & 127;
        g_Wb0h[n * FIN + k] = __float2half_rn(w[k * 256 + n]);
    }
}

// g_Wch[n][k], n interleaved (2j=z, 2j+1=h)
__global__ void k_build_wc(const float* __restrict__ czw, const float* __restrict__ chw,
                           const float* __restrict__ lzw, const float* __restrict__ lhw) {
    __shared__ float rz[128], rh[128];
    int k = blockIdx.x;        // 0..255
    int j = threadIdx.x;       // 0..127
    rz[j] = czw[k * 128 + j];
    rh[j] = chw[k * 128 + j];
    __syncthreads();
    float az = 0.f, ah = 0.f;
    #pragma unroll 4
    for (int t = 0; t < 128; t++) {
        az += rz[t] * lzw[t * 128 + j];
        ah += rh[t] * lhw[t * 128 + j];
    }
    g_Wch[(2 * j)     * 256 + k] = __float2half_rn(az);
    g_Wch[(2 * j + 1) * 256 + k] = __float2half_rn(ah);
}

__global__ void k_build_bc(const float* __restrict__ czb, const float* __restrict__ chb,
                           const float* __restrict__ lzw, const float* __restrict__ lhw,
                           const float* __restrict__ lzb, const float* __restrict__ lhb) {
    int j = threadIdx.x;
    float az = lzb[j], ah = lhb[j];
    #pragma unroll 4
    for (int t = 0; t < 128; t++) {
        az += czb[t] * lzw[t * 128 + j];
        ah += chb[t] * lhw[t * 128 + j];
    }
    g_bc[2 * j]     = az;
    g_bc[2 * j + 1] = ah;
}

// ---------------- fused double-GEMM (fp16, ldmatrix): G = relu(x@W0+b) @ Wc ----------------
#define ASA_B   0
#define ASA_SZB 5120
#define BSA_B   10240
#define BSA_SZB 20480
#define AS2_B   0
#define LDA  40
#define LDB  40
#define LDA2 264
#define BSB_B   51200
#define BSB_SZB 20480
#define SMEM_BYTES 92160

__global__ __launch_bounds__(256, 2) void k_gemm_fused(const float* __restrict__ bias0,
                                                       int M) {
    extern __shared__ char sm[];
    const uint32_t smb = smem_u32(sm);

    const int tid  = threadIdx.x;
    const int lane = tid & 31;
    const int w    = tid >> 5;
    const int wy   = w & 1;
    const int wx   = w >> 1;
    const int g    = lane >> 2;
    const int cq   = lane & 3;

    const int row0  = blockIdx.x * 64;
    const int woffm = wy * 32;
    const int woffn = wx * 64;

    const uint32_t lrow_a = ((lane >> 3) & 1) * 8 + (lane & 7);
    const uint32_t lk_a   = (lane >> 4) * 8;
    const uint32_t lrow_b = (lane >> 4) * 8 + (lane & 7);
    const uint32_t lk_b   = ((lane >> 3) & 1) * 8;

    float acc[2][8][4];
    #pragma unroll
    for (int mt = 0; mt < 2; mt++)
        #pragma unroll
        for (int nt = 0; nt < 8; nt++)
            #pragma unroll
            for (int i = 0; i < 4; i++) acc[mt][nt][i] = 0.f;

    auto load_a = [&](int st, int kb) {
        {
            int r = tid >> 2, q = tid & 3;
            int gr = row0 + r;
            int ok = (gr < M);
            const __half* gp = g_Xh + (size_t)(ok ? gr : (M - 1)) * FIN + kb + q * 8;
            cp_async16(smb + ASA_B + st * ASA_SZB + (uint32_t)(r * LDA + q * 8) * 2u,
                       gp, ok ? 16 : 0);
        }
        #pragma unroll
        for (int l = 0; l < 4; l++) {
            int idx = tid + l * 256;
            int n = idx >> 2, q = idx & 3;
            cp_async16(smb + BSA_B + st * BSA_SZB + (uint32_t)(n * LDB + q * 8) * 2u,
                       g_Wb0h + (size_t)n * FIN + kb + q * 8, 16);
        }
    };

    load_a(0, 0);
    CP_COMMIT();

    for (int kbi = 0; kbi < 4; kbi++) {
        if (kbi + 1 < 4) load_a((kbi + 1) & 1, (kbi + 1) * 32);
        CP_COMMIT();
        CP_WAIT1();
        __syncthreads();
        const uint32_t abase = smb + ASA_B + (kbi & 1) * ASA_SZB
                             + ((woffm + lrow_a) * LDA + lk_a) * 2u;
        const uint32_t bbase = smb + BSA_B + (kbi & 1) * BSA_SZB
                             + ((woffn + lrow_b) * LDB + lk_b) * 2u;

        #pragma unroll
        for (int kk = 0; kk < 32; kk += 16) {
            uint32_t af[2][4], bf[8][2];
            LDSM_X4(af[0][0], af[0][1], af[0][2], af[0][3], abase + kk * 2u);
            LDSM_X4(af[1][0], af[1][1], af[1][2], af[1][3],
                    abase + (16 * LDA + kk) * 2u);
            #pragma unroll
            for (int p = 0; p < 4; p++)
                LDSM_X4(bf[2 * p][0], bf[2 * p][1], bf[2 * p + 1][0], bf[2 * p + 1][1],
                        bbase + (p * 16 * LDB + kk) * 2u);
            #pragma unroll
            for (int mt = 0; mt < 2; mt++)
                #pragma unroll
                for (int nt = 0; nt < 8; nt++)
                    mma_f16(acc[mt][nt], af[mt], bf[nt]);
        }
        __syncthreads();
    }

    // start streaming Wc chunk 0 into Bsb (non-aliased) to overlap with epilogue
    {
        #pragma unroll
        for (int l = 0; l < 4; l++) {
            int idx = tid + l * 256;
            int n = idx >> 2, q = idx & 3;
            cp_async16(smb + BSB_B + (uint32_t)(n * LDB + q * 8) * 2u,
                       g_Wch + (size_t)n * 256 + q * 8, 16);
        }
        CP_COMMIT();
    }

    // stage-A epilogue: relu + bias -> fp16 -> As2 [64][264]
    #pragma unroll
    for (int mt = 0; mt < 2; mt++) {
        int r0 = woffm + mt * 16 + g;
        int r1 = r0 + 8;
        #pragma unroll
        for (int nt = 0; nt < 8; nt++) {
            int col = woffn + nt * 8 + 2 * cq;
            float b0 = bias0[col], b1 = bias0[col + 1];
            __half2 v0 = __floats2half2_rn(fmaxf(acc[mt][nt][0] + b0, 0.f),
                                           fmaxf(acc[mt][nt][1] + b1, 0.f));
            __half2 v1 = __floats2half2_rn(fmaxf(acc[mt][nt][2] + b0, 0.f),
                                           fmaxf(acc[mt][nt][3] + b1, 0.f));
            *(__half2*)(sm + AS2_B + (r0 * LDA2 + col) * 2) = v0;
            *(__half2*)(sm + AS2_B + (r1 * LDA2 + col) * 2) = v1;
        }
    }
    __syncthreads();

    // ---- stage B: G = As2 @ Wct, K=256, 8 chunks of 32 ----
    #pragma unroll
    for (int mt = 0; mt < 2; mt++)
        #pragma unroll
        for (int nt = 0; nt < 8; nt++)
            #pragma unroll
            for (int i = 0; i < 4; i++) acc[mt][nt][i] = 0.f;

    auto load_b = [&](int st, int kc) {
        #pragma unroll
        for (int l = 0; l < 4; l++) {
            int idx = tid + l * 256;
            int n = idx >> 2, q = idx & 3;
            cp_async16(smb + BSB_B + st * BSB_SZB + (uint32_t)(n * LDB + q * 8) * 2u,
                       g_Wch + (size_t)n * 256 + kc + q * 8, 16);
        }
    };

    const uint32_t a2base = smb + AS2_B + ((woffm + lrow_a) * LDA2 + lk_a) * 2u;
    for (int it = 0; it < 8; it++) {
        if (it + 1 < 8) load_b((it + 1) & 1, (it + 1) * 32);
        CP_COMMIT();
        CP_WAIT1();
        __syncthreads();
        const uint32_t bbase = smb + BSB_B + (it & 1) * BSB_SZB
                             + ((woffn + lrow_b) * LDB + lk_b) * 2u;
        const int kg = it * 32;

        #pragma unroll
        for (int kk = 0; kk < 32; kk += 16) {
            uint32_t af[2][4], bf[8][2];
            LDSM_X4(af[0][0], af[0][1], af[0][2], af[0][3], a2base + (kg + kk) * 2u);
            LDSM_X4(af[1][0], af[1][1], af[1][2], af[1][3],
                    a2base + (16 * LDA2 + kg + kk) * 2u);
            #pragma unroll
            for (int p = 0; p < 4; p++)
                LDSM_X4(bf[2 * p][0], bf[2 * p][1], bf[2 * p + 1][0], bf[2 * p + 1][1],
                        bbase + (p * 16 * LDB + kk) * 2u);
            #pragma unroll
            for (int mt = 0; mt < 2; mt++)
                #pragma unroll
                for (int nt = 0; nt < 8; nt++)
                    mma_f16(acc[mt][nt], af[mt], bf[nt]);
        }
        __syncthreads();
    }

    // stage-B epilogue: fp16 gates to g_Gh (guarded)
    #pragma unroll
    for (int mt = 0; mt < 2; mt++) {
        int r0 = row0 + woffm + mt * 16 + g;
        int r1 = r0 + 8;
        #pragma unroll
        for (int nt = 0; nt < 8; nt++) {
            int col = woffn + nt * 8 + 2 * cq;
            if (r0 < M)
                *(__half2*)(g_Gh + (size_t)r0 * 256 + col) =
                    __floats2half2_rn(acc[mt][nt][0], acc[mt][nt][1]);
            if (r1 < M)
                *(__half2*)(g_Gh + (size_t)r1 * 256 + col) =
                    __floats2half2_rn(acc[mt][nt][2], acc[mt][nt][3]);
        }
    }
}

// ---------------- fused aggregate + bias + GRU + output head (warp-per-node, fp16 G) ----------------
__device__ __forceinline__ void acc8(float* a, uint4 u, float c) {
    float2 f0 = __half22float2(*(__half2*)&u.x);
    float2 f1 = __half22float2(*((__half2*)&u.x + 1));
    float2 f2 = __half22float2(*(__half2*)&u.z);
    float2 f3 = __half22float2(*((__half2*)&u.z + 1));
    a[0] += c * f0.x; a[1] += c * f0.y;
    a[2] += c * f1.x; a[3] += c * f1.y;
    a[4] += c * f2.x; a[5] += c * f2.y;
    a[6] += c * f3.x; a[7] += c * f3.y;
}

__global__ __launch_bounds__(256) void k_agg_gru(const float* __restrict__ fcw,
                                                 const float* __restrict__ fcb,
                                                 float* __restrict__ hout,
                                                 float* __restrict__ out) {
    const int wid  = threadIdx.x >> 5;
    const int lane = threadIdx.x & 31;
    const int n    = blockIdx.x * 8 + wid;
    if (n >= Nn) return;

    const uint4* G16 = (const uint4*)g_Gh;     // row stride 32 uint4

    float a[8];
    #pragma unroll
    for (int j = 0; j < 8; j++) a[j] = 0.f;

    const int beg = g_rowptr[n];
    const int count = g_count[n];
    const int nf = count < 32 ? count : 32;

    int2 my = make_int2(0, 0);
    if (lane < nf) my = g_csr[beg + lane];

    int e = 0;
    for (; e + 4 <= nf; e += 4) {
        int s0 = __shfl_sync(0xffffffffu, my.x, e);
        int s1 = __shfl_sync(0xffffffffu, my.x, e + 1);
        int s2 = __shfl_sync(0xffffffffu, my.x, e + 2);
        int s3 = __shfl_sync(0xffffffffu, my.x, e + 3);
        float c0 = __int_as_float(__shfl_sync(0xffffffffu, my.y, e));
        float c1 = __int_as_float(__shfl_sync(0xffffffffu, my.y, e + 1));
        float c2 = __int_as_float(__shfl_sync(0xffffffffu, my.y, e + 2));
        float c3 = __int_as_float(__shfl_sync(0xffffffffu, my.y, e + 3));
        uint4 u0 = G16[(size_t)s0 * 32 + lane];
        uint4 u1 = G16[(size_t)s1 * 32 + lane];
        uint4 u2 = G16[(size_t)s2 * 32 + lane];
        uint4 u3 = G16[(size_t)s3 * 32 + lane];
        acc8(a, u0, c0); acc8(a, u1, c1); acc8(a, u2, c2); acc8(a, u3, c3);
    }
    for (; e < nf; e++) {
        int   s = __shfl_sync(0xffffffffu, my.x, e);
        float c = __int_as_float(__shfl_sync(0xffffffffu, my.y, e));
        acc8(a, G16[(size_t)s * 32 + lane], c);
    }
    for (int ee = 32; ee < count; ee++) {      // ~never taken (Poisson(8))
        int2 p = g_csr[beg + ee];
        acc8(a, G16[(size_t)p.x * 32 + lane], __int_as_float(p.y));
    }

    const float di  = g_dinv[n];
    const float di2 = di * di;
    float s[8];
    {
        uint4 us = G16[(size_t)n * 32 + lane];
        float2 f0 = __half22float2(*(__half2*)&us.x);
        float2 f1 = __half22float2(*((__half2*)&us.x + 1));
        float2 f2 = __half22float2(*(__half2*)&us.z);
        float2 f3 = __half22float2(*((__half2*)&us.z + 1));
        s[0] = f0.x; s[1] = f0.y; s[2] = f1.x; s[3] = f1.y;
        s[4] = f2.x; s[5] = f2.y; s[6] = f3.x; s[7] = f3.y;
    }
    float4 bc0 = ((const float4*)g_bc)[2 * lane];
    float4 bc1 = ((const float4*)g_bc)[2 * lane + 1];
    float gate[8];
    gate[0] = a[0] * di + di2 * s[0] + bc0.x;
    gate[1] = a[1] * di + di2 * s[1] + bc0.y;
    gate[2] = a[2] * di + di2 * s[2] + bc0.z;
    gate[3] = a[3] * di + di2 * s[3] + bc0.w;
    gate[4] = a[4] * di + di2 * s[4] + bc1.x;
    gate[5] = a[5] * di + di2 * s[5] + bc1.y;
    gate[6] = a[6] * di + di2 * s[6] + bc1.z;
    gate[7] = a[7] * di + di2 * s[7] + bc1.w;

    float h[4];
    #pragma unroll
    for (int i = 0; i < 4; i++) {
        float z = 1.f / (1.f + expf(-gate[2 * i]));
        h[i] = (1.f - z) * tanhf(gate[2 * i + 1]);
    }

    *(float4*)(hout + (size_t)n * 128 + 4 * lane) = make_float4(h[0], h[1], h[2], h[3]);

    float4 wv = ((const float4*)fcw)[lane];
    float prod = fmaxf(h[0], 0.f) * wv.x + fmaxf(h[1], 0.f) * wv.y
               + fmaxf(h[2], 0.f) * wv.z + fmaxf(h[3], 0.f) * wv.w;
    #pragma unroll
    for (int o = 16; o; o >>= 1) prod += __shfl_xor_sync(0xffffffffu, prod, o);
    if (lane == 0) out[n] = prod + fcb[0];
}

// ---------------- launch (dual-stream fork/join) ----------------
extern "C" void kernel_launch(void* const* d_in, const int* in_sizes, int n_in,
                              void* d_out, int out_size) {
    const float* x     = (const float*)d_in[0];
    const int*   ei    = (const int*)d_in[1];
    const float* ew    = (const float*)d_in[2];
    const float* fc0_w = (const float*)d_in[3];
    const float* fc0_b = (const float*)d_in[4];
    // d_in[5] = att: softmax over one element == 1.0
    const float* czw   = (const float*)d_in[6];
    const float* czb   = (const float*)d_in[7];
    const float* lzw   = (const float*)d_in[8];
    const float* lzb   = (const float*)d_in[9];
    // d_in[10..13] dead (H0 == 0 kills the R branch)
    const float* chw   = (const float*)d_in[14];
    const float* chb   = (const float*)d_in[15];
    const float* lhw   = (const float*)d_in[16];
    const float* lhb   = (const float*)d_in[17];
    const float* fcw   = (const float*)d_in[18];
    const float* fcb   = (const float*)d_in[19];

    const int* src = ei;
    const int* dst = ei + Ee;

    float* out  = (float*)d_out;
    float* hout = out + Nn;

    const int nb = (Nn + 1023) / 1024;
    const int gM = (Nn + 63) / 64;

    static cudaStream_t s1;
    static cudaEvent_t evFork, evJoin;
    static bool once = false;
    if (!once) {
        cudaFuncSetAttribute(k_gemm_fused, cudaFuncAttributeMaxDynamicSharedMemorySize, SMEM_BYTES);
        cudaStreamCreateWithFlags(&s1, cudaStreamNonBlocking);
        cudaEventCreateWithFlags(&evFork, cudaEventDisableTiming);
        cudaEventCreateWithFlags(&evJoin, cudaEventDisableTiming);
        once = true;
    }

    // fork point: csr chain (s1) is independent of the GEMM chain (default stream)
    cudaEventRecord(evFork, 0);

    // ---- GEMM chain on the capture (default) stream; gemm = kernel-launch index 3 ----
    k_prep_x<<<(Nn * FIN / 2 + 255) / 256, 256>>>(x);
    k_prep_b0<<<(FIN * 256 + 255) / 256, 256>>>(fc0_w);
    k_build_wc<<<256, 128>>>(czw, chw, lzw, lhw);

    k_gemm_fused<<<gM, 256, SMEM_BYTES>>>(fc0_b, Nn);   // index 3 (ncu control)

    // ---- csr chain on s1, depends only on the fork event ----
    cudaStreamWaitEvent(s1, evFork, 0);
    k_init<<<(Nn + 255) / 256, 256, 0, s1>>>();
    k_edge_accum<<<(Ee + 255) / 256, 256, 0, s1>>>(dst, ew);
    k_dinv<<<(Nn + 255) / 256, 256, 0, s1>>>();
    k_scan_block<<<nb, 1024, 0, s1>>>();
    k_scan_sums<<<1, 32, 0, s1>>>(nb);
    k_scan_add<<<nb, 1024, 0, s1>>>();
    k_fill<<<(Ee + 255) / 256, 256, 0, s1>>>(src, dst, ew);
    k_build_bc<<<1, 128, 0, s1>>>(czb, chb, lzw, lhw, lzb, lhb);
    cudaEventRecord(evJoin, s1);

    // join: aggregation needs both the GEMM output and the csr structures
    cudaStreamWaitEvent(0, evJoin, 0);
    k_agg_gru<<<(Nn + 7) / 8, 256>>>(fcw, fcb, hout, out);
}